// round 12
// baseline (speedup 1.0000x reference)
#include <cuda_runtime.h>
#include <math_constants.h>

// ---------------- problem constants ----------------
#define NN 100000      // nodes
#define NE 3200000     // edges
#define NG 512         // graphs
#define BN_EPS 1e-5f
#define NBLK ((NN + 255) / 256)   // 391

typedef unsigned long long ull;

// ---------------- packed f32x2 helpers ----------------
__device__ __forceinline__ ull pack2(float lo, float hi) {
    ull r; asm("mov.b64 %0, {%1, %2};" : "=l"(r) : "f"(lo), "f"(hi)); return r;
}
__device__ __forceinline__ ull dup2(float v) {
    ull r; asm("mov.b64 %0, {%1, %1};" : "=l"(r) : "f"(v)); return r;
}
__device__ __forceinline__ void unpack2(ull v, float& lo, float& hi) {
    asm("mov.b64 {%0, %1}, %2;" : "=f"(lo), "=f"(hi) : "l"(v));
}
__device__ __forceinline__ void ffma2(ull& d, ull a, ull b) {
    asm("fma.rn.f32x2 %0, %1, %2, %0;" : "+l"(d) : "l"(a), "l"(b));
}

// ---------------- device scratch (no allocs allowed) ----------------
__device__ int    d_cnt[NN];
__device__ int    d_rowptr[NN + 1];
__device__ int    d_wp[NN];
__device__ ull    d_tile[512];            // lookback scan state
__device__ float2 d_csr[NE];              // (src as int bits, dis[src])
__device__ float  d_dis[NN];
__device__ float  d_y1 [(size_t)NN * 8];
__device__ float  d_y2 [(size_t)NN * 32];
__device__ float  d_y3 [(size_t)NN * 128];
__device__ float  d_stats[256];
__device__ float  d_scale[128];
__device__ float  d_shift[128];
__device__ int    d_gstart[NG];
__device__ int    d_gend[NG];
__device__ int    d_is64_edge;
__device__ int    d_is64_batch;
__device__ int    d_tick;
__device__ int    d_bar;

// ---------------- BN finalize epilogue ----------------
__device__ __forceinline__ void bn_finalize(int FO, const float* gam, const float* bet) {
    __threadfence();
    __shared__ int isLast;
    if (threadIdx.x == 0) isLast = (atomicAdd(&d_tick, 1) == (int)gridDim.x - 1);
    __syncthreads();
    if (isLast) {
        if ((int)threadIdx.x < FO) {
            int c = threadIdx.x;
            float sum = atomicAdd(&d_stats[c], 0.f);
            float sq  = atomicAdd(&d_stats[128 + c], 0.f);
            float m   = sum * (1.0f / NN);
            float var = sq * (1.0f / NN) - m * m;
            float scv = gam[c] * rsqrtf(var + BN_EPS);
            d_scale[c] = scv;
            d_shift[c] = bet[c] - m * scv;
            d_stats[c] = 0.f;
            d_stats[128 + c] = 0.f;
        }
        if (threadIdx.x == 0) d_tick = 0;
    }
}

// ---------------- prep: zero state + dtype detection ----------------
__global__ void k_prep(const void* ei, const void* bi) {
    int i = blockIdx.x * blockDim.x + threadIdx.x;
    if (i < NN) d_cnt[i] = 0;
    if (i < 512) d_tile[i] = 0ULL;
    if (i < 256) d_stats[i] = 0.f;
    if (i == 0) { d_tick = 0; d_bar = 0; }
    if (blockIdx.x == 0) {
        long long v = ((const long long*)ei)[(size_t)threadIdx.x * 6000];
        int ok = (v >= 0 && v < NN);
        ok = __syncthreads_and(ok);
        if (threadIdx.x == 0) d_is64_edge = ok;
    } else if (blockIdx.x == 1) {
        long long v = ((const long long*)bi)[(size_t)threadIdx.x * 195];
        int ok = (v >= 0 && v < NG);
        ok = __syncthreads_and(ok);
        if (threadIdx.x == 0) d_is64_batch = ok;
    }
}

// ---------------- count in-degrees + graph boundaries ----------------
__global__ void k_countbounds(const void* ei, const void* bi) {
    int e = blockIdx.x * blockDim.x + threadIdx.x;
    if (e < NE) {
        int d;
        if (d_is64_edge) d = (int)((const long long*)ei)[(size_t)NE + e];
        else             d = ((const int*)ei)[NE + e];
        atomicAdd(&d_cnt[d], 1);
    }
    if (e < NN) {
        int i = e, g, gp, gn;
        if (d_is64_batch) {
            const long long* p = (const long long*)bi;
            g  = (int)p[i];
            gp = (i > 0)      ? (int)p[i - 1] : -1;
            gn = (i < NN - 1) ? (int)p[i + 1] : NG;
        } else {
            const int* p = (const int*)bi;
            g  = p[i];
            gp = (i > 0)      ? p[i - 1] : -1;
            gn = (i < NN - 1) ? p[i + 1] : NG;
        }
        if (g != gp) d_gstart[g] = i;
        if (g != gn) d_gend[g] = i + 1;
    }
}

// ---------------- scan (lookback) + grid barrier + CSR fill, one kernel ----------------
__global__ void k_scanfill(const void* ei) {
    __shared__ int s[256];
    __shared__ int sExcl;
    int b = blockIdx.x, t = threadIdx.x;
    int i = b * 256 + t;
    int orig = (i < NN) ? d_cnt[i] : 0;
    s[t] = orig;
    __syncthreads();
    for (int o = 1; o < 256; o <<= 1) {
        int u = (t >= o) ? s[t - o] : 0;
        __syncthreads();
        s[t] += u;
        __syncthreads();
    }
    int incl = s[t];
    int agg  = s[255];
    if (t == 0) {
        if (b == 0) {
            sExcl = 0;
            *(volatile ull*)&d_tile[0] = (2ULL << 32) | (unsigned)agg;
        } else {
            *(volatile ull*)&d_tile[b] = (1ULL << 32) | (unsigned)agg;
            int excl = 0, p = b - 1;
            while (1) {
                ull v;
                do { v = *(volatile ull*)&d_tile[p]; } while ((unsigned)(v >> 32) == 0u);
                excl += (int)(unsigned)v;
                if ((unsigned)(v >> 32) == 2u) break;
                p--;
            }
            *(volatile ull*)&d_tile[b] = (2ULL << 32) | (unsigned)(excl + agg);
            sExcl = excl;
        }
    }
    __syncthreads();
    int ex = sExcl + incl - orig;
    if (i < NN) {
        d_rowptr[i] = ex;
        d_wp[i] = ex;
        d_dis[i] = rsqrtf((float)(orig + 1));
    }
    if (i == 0) d_rowptr[NN] = NE;
    // ---- grid barrier (all 391 blocks co-resident) ----
    __threadfence();
    __syncthreads();
    if (t == 0) {
        atomicAdd(&d_bar, 1);
        while (*(volatile int*)&d_bar < (int)gridDim.x) {}
    }
    __syncthreads();
    __threadfence();
    // ---- fill ----
    int stride = gridDim.x * blockDim.x;
    for (int e = b * 256 + t; e < NE; e += stride) {
        int sN, dN;
        if (d_is64_edge) {
            const long long* p = (const long long*)ei;
            sN = (int)p[e];
            dN = (int)p[(size_t)NE + e];
        } else {
            const int* p = (const int*)ei;
            sN = p[e];
            dN = p[NE + e];
        }
        int pos = atomicAdd(&d_wp[dN], 1);
        d_csr[pos] = make_float2(__int_as_float(sN), d_dis[sN]);
    }
}

// ---------------- layer 1: agg(F=2) 2-threads/node + GEMM 2->8 + relu + BN stats ----------------
__global__ void k_l1(const float* __restrict__ x,
                     const float* __restrict__ W1, const float* __restrict__ b1,
                     const float* __restrict__ g1, const float* __restrict__ be1) {
    __shared__ float sW[16], sb[8], sst[32];
    if (threadIdx.x < 16) sW[threadIdx.x] = W1[threadIdx.x];
    if (threadIdx.x < 8)  sb[threadIdx.x] = b1[threadIdx.x];
    if (threadIdx.x < 32) sst[threadIdx.x] = 0.f;
    __syncthreads();
    int gid = blockIdx.x * blockDim.x + threadIdx.x;
    int i   = gid >> 1;
    int sub = gid & 1;                    // pair = adjacent lanes, never split
    bool act = i < NN;
    float ax = 0.f, ay = 0.f, di = 0.f;
    int e = 0, end = 0;
    if (act) {
        di = d_dis[i];
        int beg = d_rowptr[i];
        end = d_rowptr[i + 1];
        e = beg + sub;
        if (sub == 0) {
            const float2 self = ((const float2*)x)[i];
            ax = self.x * di;
            ay = self.y * di;
        }
    }
    const float2* x2 = (const float2*)x;
    for (; e + 6 < end; e += 8) {         // 4 edges per thread per iter (stride 2)
        float2 p0 = __ldg(&d_csr[e]),     p1 = __ldg(&d_csr[e + 2]);
        float2 p2 = __ldg(&d_csr[e + 4]), p3 = __ldg(&d_csr[e + 6]);
        float2 v0 = __ldg(&x2[__float_as_int(p0.x)]);
        float2 v1 = __ldg(&x2[__float_as_int(p1.x)]);
        float2 v2 = __ldg(&x2[__float_as_int(p2.x)]);
        float2 v3 = __ldg(&x2[__float_as_int(p3.x)]);
        ax += v0.x * p0.y + v1.x * p1.y + v2.x * p2.y + v3.x * p3.y;
        ay += v0.y * p0.y + v1.y * p1.y + v2.y * p2.y + v3.y * p3.y;
    }
    for (; e < end; e += 2) {
        float2 p = __ldg(&d_csr[e]);
        float2 v = __ldg(&x2[__float_as_int(p.x)]);
        ax += v.x * p.y;
        ay += v.y * p.y;
    }
    // combine the pair (all lanes participate)
    ax += __shfl_xor_sync(0xFFFFFFFFu, ax, 1);
    ay += __shfl_xor_sync(0xFFFFFFFFu, ay, 1);
    float o[8];
#pragma unroll
    for (int k = 0; k < 8; k++) o[k] = 0.f;
    if (act && sub == 0) {
        ax *= di; ay *= di;
#pragma unroll
        for (int k = 0; k < 8; k++)
            o[k] = fmaxf(fmaf(ax, sW[k], fmaf(ay, sW[8 + k], sb[k])), 0.f);
        float4* yo = (float4*)(d_y1 + (size_t)i * 8);
        yo[0] = make_float4(o[0], o[1], o[2], o[3]);
        yo[1] = make_float4(o[4], o[5], o[6], o[7]);
    }
#pragma unroll
    for (int k = 0; k < 8; k++) {
        float s = o[k], q = o[k] * o[k];
#pragma unroll
        for (int off = 16; off; off >>= 1) {
            s += __shfl_xor_sync(0xFFFFFFFFu, s, off);
            q += __shfl_xor_sync(0xFFFFFFFFu, q, off);
        }
        if ((threadIdx.x & 31) == 0) {
            atomicAdd(&sst[k], s);
            atomicAdd(&sst[16 + k], q);
        }
    }
    __syncthreads();
    if (threadIdx.x < 8) {
        atomicAdd(&d_stats[threadIdx.x], sst[threadIdx.x]);
        atomicAdd(&d_stats[128 + threadIdx.x], sst[16 + threadIdx.x]);
    }
    bn_finalize(8, g1, be1);
}

// ---------------- layer 2: agg(F=8, BN folded) + GEMM 8->32 + relu + BN stats ----------------
__global__ void k_l2(const float* __restrict__ W2, const float* __restrict__ b2,
                     const float* __restrict__ g2, const float* __restrict__ be2) {
    __shared__ float sW[8 * 32], sb[32], sst[64];
    for (int k = threadIdx.x; k < 256; k += blockDim.x) sW[k] = W2[k];
    if (threadIdx.x < 32) sb[threadIdx.x] = b2[threadIdx.x];
    if (threadIdx.x < 64) sst[threadIdx.x] = 0.f;
    __syncthreads();
    int lane = threadIdx.x & 31;
    int sub  = lane >> 3;
    int ln   = lane & 7;
    int gwarp  = (blockIdx.x * blockDim.x + threadIdx.x) >> 5;
    int nwarps = (gridDim.x * blockDim.x) >> 5;
    float sc = d_scale[ln], sh = d_shift[ln];
    float ls0 = 0.f, ls1 = 0.f, ls2 = 0.f, ls3 = 0.f;
    float lq0 = 0.f, lq1 = 0.f, lq2 = 0.f, lq3 = 0.f;
    for (int n0 = gwarp * 4; n0 < NN; n0 += nwarps * 4) {
        int node = n0 + sub;
        bool act = node < NN;
        int e = 0, end = 0;
        float acc0 = 0.f, acc1 = 0.f, di = 0.f;
        if (act) {
            di = d_dis[node];
            e = d_rowptr[node];
            end = d_rowptr[node + 1];
            acc0 = fmaf(d_y1[(size_t)node * 8 + ln], sc, sh) * di;
        }
        for (; e + 8 <= end; e += 8) {
            float2 p0 = __ldg(&d_csr[e]),     p1 = __ldg(&d_csr[e + 1]);
            float2 p2 = __ldg(&d_csr[e + 2]), p3 = __ldg(&d_csr[e + 3]);
            float2 p4 = __ldg(&d_csr[e + 4]), p5 = __ldg(&d_csr[e + 5]);
            float2 p6 = __ldg(&d_csr[e + 6]), p7 = __ldg(&d_csr[e + 7]);
            float h0 = __ldg(&d_y1[(size_t)__float_as_int(p0.x) * 8 + ln]);
            float h1 = __ldg(&d_y1[(size_t)__float_as_int(p1.x) * 8 + ln]);
            float h2 = __ldg(&d_y1[(size_t)__float_as_int(p2.x) * 8 + ln]);
            float h3 = __ldg(&d_y1[(size_t)__float_as_int(p3.x) * 8 + ln]);
            float h4 = __ldg(&d_y1[(size_t)__float_as_int(p4.x) * 8 + ln]);
            float h5 = __ldg(&d_y1[(size_t)__float_as_int(p5.x) * 8 + ln]);
            float h6 = __ldg(&d_y1[(size_t)__float_as_int(p6.x) * 8 + ln]);
            float h7 = __ldg(&d_y1[(size_t)__float_as_int(p7.x) * 8 + ln]);
            acc0 = fmaf(fmaf(h0, sc, sh), p0.y, acc0);
            acc1 = fmaf(fmaf(h1, sc, sh), p1.y, acc1);
            acc0 = fmaf(fmaf(h2, sc, sh), p2.y, acc0);
            acc1 = fmaf(fmaf(h3, sc, sh), p3.y, acc1);
            acc0 = fmaf(fmaf(h4, sc, sh), p4.y, acc0);
            acc1 = fmaf(fmaf(h5, sc, sh), p5.y, acc1);
            acc0 = fmaf(fmaf(h6, sc, sh), p6.y, acc0);
            acc1 = fmaf(fmaf(h7, sc, sh), p7.y, acc1);
        }
        for (; e < end; e++) {
            float2 p = __ldg(&d_csr[e]);
            float hv = __ldg(&d_y1[(size_t)__float_as_int(p.x) * 8 + ln]);
            acc0 = fmaf(fmaf(hv, sc, sh), p.y, acc0);
        }
        float acc = (acc0 + acc1) * di;
        float4 yv = make_float4(sb[ln * 4], sb[ln * 4 + 1], sb[ln * 4 + 2], sb[ln * 4 + 3]);
#pragma unroll
        for (int f = 0; f < 8; f++) {
            float av = __shfl_sync(0xFFFFFFFFu, acc, f, 8);
            const float* wr = &sW[f * 32 + ln * 4];
            yv.x = fmaf(av, wr[0], yv.x);
            yv.y = fmaf(av, wr[1], yv.y);
            yv.z = fmaf(av, wr[2], yv.z);
            yv.w = fmaf(av, wr[3], yv.w);
        }
        yv.x = fmaxf(yv.x, 0.f); yv.y = fmaxf(yv.y, 0.f);
        yv.z = fmaxf(yv.z, 0.f); yv.w = fmaxf(yv.w, 0.f);
        if (act) {
            ((float4*)(d_y2 + (size_t)node * 32))[ln] = yv;
            ls0 += yv.x; lq0 += yv.x * yv.x;
            ls1 += yv.y; lq1 += yv.y * yv.y;
            ls2 += yv.z; lq2 += yv.z * yv.z;
            ls3 += yv.w; lq3 += yv.w * yv.w;
        }
    }
#pragma unroll
    for (int off = 8; off <= 16; off <<= 1) {
        ls0 += __shfl_xor_sync(0xFFFFFFFFu, ls0, off);
        ls1 += __shfl_xor_sync(0xFFFFFFFFu, ls1, off);
        ls2 += __shfl_xor_sync(0xFFFFFFFFu, ls2, off);
        ls3 += __shfl_xor_sync(0xFFFFFFFFu, ls3, off);
        lq0 += __shfl_xor_sync(0xFFFFFFFFu, lq0, off);
        lq1 += __shfl_xor_sync(0xFFFFFFFFu, lq1, off);
        lq2 += __shfl_xor_sync(0xFFFFFFFFu, lq2, off);
        lq3 += __shfl_xor_sync(0xFFFFFFFFu, lq3, off);
    }
    if (lane < 8) {
        atomicAdd(&sst[ln * 4 + 0], ls0); atomicAdd(&sst[32 + ln * 4 + 0], lq0);
        atomicAdd(&sst[ln * 4 + 1], ls1); atomicAdd(&sst[32 + ln * 4 + 1], lq1);
        atomicAdd(&sst[ln * 4 + 2], ls2); atomicAdd(&sst[32 + ln * 4 + 2], lq2);
        atomicAdd(&sst[ln * 4 + 3], ls3); atomicAdd(&sst[32 + ln * 4 + 3], lq3);
    }
    __syncthreads();
    if (threadIdx.x < 32) {
        atomicAdd(&d_stats[threadIdx.x], sst[threadIdx.x]);
        atomicAdd(&d_stats[128 + threadIdx.x], sst[32 + threadIdx.x]);
    }
    bn_finalize(32, g2, be2);
}

// ---------------- layer 3: agg + GEMM 32->128 (4-node batched, f32x2) + BN stats ----------------
__global__ void k_l3(const float* __restrict__ W3, const float* __restrict__ b3,
                     const float* __restrict__ g3, const float* __restrict__ be3) {
    __shared__ ull   sW[2048];
    __shared__ float sb[128];
    __shared__ float bs[256];
    for (int k = threadIdx.x; k < 2048; k += blockDim.x)
        sW[k] = ((const ull*)W3)[k];
    if (threadIdx.x < 128) sb[threadIdx.x] = b3[threadIdx.x];
    bs[threadIdx.x] = 0.f;
    __syncthreads();
    int lane = threadIdx.x & 31;
    int gwarp  = (blockIdx.x * blockDim.x + threadIdx.x) >> 5;
    int nwarps = (gridDim.x * blockDim.x) >> 5;
    float sc = d_scale[lane], sh = d_shift[lane];
    ull bias01 = pack2(sb[lane * 4], sb[lane * 4 + 1]);
    ull bias23 = pack2(sb[lane * 4 + 2], sb[lane * 4 + 3]);
    float ls0 = 0.f, ls1 = 0.f, ls2 = 0.f, ls3 = 0.f;
    float lq0 = 0.f, lq1 = 0.f, lq2 = 0.f, lq3 = 0.f;
    for (int n0 = gwarp * 4; n0 < NN; n0 += nwarps * 4) {
        float accs[4];
#pragma unroll
        for (int nb = 0; nb < 4; nb++) {
            int node = n0 + nb;
            float acc0 = 0.f, acc1 = 0.f, di = 0.f;
            if (node < NN) {
                di = d_dis[node];
                int e = d_rowptr[node], end = d_rowptr[node + 1];
                acc0 = fmaf(d_y2[(size_t)node * 32 + lane], sc, sh) * di;
                for (; e + 8 <= end; e += 8) {
                    float2 p0 = __ldg(&d_csr[e]),     p1 = __ldg(&d_csr[e + 1]);
                    float2 p2 = __ldg(&d_csr[e + 2]), p3 = __ldg(&d_csr[e + 3]);
                    float2 p4 = __ldg(&d_csr[e + 4]), p5 = __ldg(&d_csr[e + 5]);
                    float2 p6 = __ldg(&d_csr[e + 6]), p7 = __ldg(&d_csr[e + 7]);
                    float h0 = __ldg(&d_y2[(size_t)__float_as_int(p0.x) * 32 + lane]);
                    float h1 = __ldg(&d_y2[(size_t)__float_as_int(p1.x) * 32 + lane]);
                    float h2 = __ldg(&d_y2[(size_t)__float_as_int(p2.x) * 32 + lane]);
                    float h3 = __ldg(&d_y2[(size_t)__float_as_int(p3.x) * 32 + lane]);
                    float h4 = __ldg(&d_y2[(size_t)__float_as_int(p4.x) * 32 + lane]);
                    float h5 = __ldg(&d_y2[(size_t)__float_as_int(p5.x) * 32 + lane]);
                    float h6 = __ldg(&d_y2[(size_t)__float_as_int(p6.x) * 32 + lane]);
                    float h7 = __ldg(&d_y2[(size_t)__float_as_int(p7.x) * 32 + lane]);
                    acc0 = fmaf(fmaf(h0, sc, sh), p0.y, acc0);
                    acc1 = fmaf(fmaf(h1, sc, sh), p1.y, acc1);
                    acc0 = fmaf(fmaf(h2, sc, sh), p2.y, acc0);
                    acc1 = fmaf(fmaf(h3, sc, sh), p3.y, acc1);
                    acc0 = fmaf(fmaf(h4, sc, sh), p4.y, acc0);
                    acc1 = fmaf(fmaf(h5, sc, sh), p5.y, acc1);
                    acc0 = fmaf(fmaf(h6, sc, sh), p6.y, acc0);
                    acc1 = fmaf(fmaf(h7, sc, sh), p7.y, acc1);
                }
                for (; e < end; e++) {
                    float2 p = __ldg(&d_csr[e]);
                    float hv = __ldg(&d_y2[(size_t)__float_as_int(p.x) * 32 + lane]);
                    acc0 = fmaf(fmaf(hv, sc, sh), p.y, acc0);
                }
            }
            accs[nb] = (acc0 + acc1) * di;
        }
        ull a01[4], a23[4];
#pragma unroll
        for (int nb = 0; nb < 4; nb++) { a01[nb] = bias01; a23[nb] = bias23; }
#pragma unroll
        for (int f = 0; f < 32; f++) {
            ull w01 = sW[f * 64 + lane * 2];
            ull w23 = sW[f * 64 + lane * 2 + 1];
#pragma unroll
            for (int nb = 0; nb < 4; nb++) {
                ull avv = dup2(__shfl_sync(0xFFFFFFFFu, accs[nb], f));
                ffma2(a01[nb], avv, w01);
                ffma2(a23[nb], avv, w23);
            }
        }
#pragma unroll
        for (int nb = 0; nb < 4; nb++) {
            int node = n0 + nb;
            if (node >= NN) break;
            float v0, v1, v2, v3;
            unpack2(a01[nb], v0, v1);
            unpack2(a23[nb], v2, v3);
            v0 = fmaxf(v0, 0.f); v1 = fmaxf(v1, 0.f);
            v2 = fmaxf(v2, 0.f); v3 = fmaxf(v3, 0.f);
            ((float4*)(d_y3 + (size_t)node * 128))[lane] = make_float4(v0, v1, v2, v3);
            ls0 += v0; lq0 += v0 * v0;
            ls1 += v1; lq1 += v1 * v1;
            ls2 += v2; lq2 += v2 * v2;
            ls3 += v3; lq3 += v3 * v3;
        }
    }
    atomicAdd(&bs[lane * 4 + 0], ls0); atomicAdd(&bs[128 + lane * 4 + 0], lq0);
    atomicAdd(&bs[lane * 4 + 1], ls1); atomicAdd(&bs[128 + lane * 4 + 1], lq1);
    atomicAdd(&bs[lane * 4 + 2], ls2); atomicAdd(&bs[128 + lane * 4 + 2], lq2);
    atomicAdd(&bs[lane * 4 + 3], ls3); atomicAdd(&bs[128 + lane * 4 + 3], lq3);
    __syncthreads();
    atomicAdd(&d_stats[threadIdx.x], bs[threadIdx.x]);
    bn_finalize(128, g3, be3);
}

// ---------------- fused max-pool (BN folded) + linear + log_softmax ----------------
__global__ void k_poolhead(const float* __restrict__ Wl, const float* __restrict__ bl,
                           float* __restrict__ out) {
    __shared__ float ssum[12];
    int g = blockIdx.x, t = threadIdx.x;
    float sc = d_scale[t], sh = d_shift[t];
    float m = -CUDART_INF_F;
    int s = d_gstart[g], e = d_gend[g];
    int i = s;
    for (; i + 4 <= e; i += 4) {
        float v0 = d_y3[(size_t)(i + 0) * 128 + t];
        float v1 = d_y3[(size_t)(i + 1) * 128 + t];
        float v2 = d_y3[(size_t)(i + 2) * 128 + t];
        float v3 = d_y3[(size_t)(i + 3) * 128 + t];
        m = fmaxf(m, fmaxf(fmaxf(v0, v1), fmaxf(v2, v3)));
    }
    for (; i < e; i++) m = fmaxf(m, d_y3[(size_t)i * 128 + t]);
    float p = fmaf(m, sc, sh);
    float a0 = p * Wl[t * 3 + 0];
    float a1 = p * Wl[t * 3 + 1];
    float a2 = p * Wl[t * 3 + 2];
#pragma unroll
    for (int o = 16; o > 0; o >>= 1) {
        a0 += __shfl_down_sync(0xFFFFFFFFu, a0, o);
        a1 += __shfl_down_sync(0xFFFFFFFFu, a1, o);
        a2 += __shfl_down_sync(0xFFFFFFFFu, a2, o);
    }
    int w = t >> 5;
    if ((t & 31) == 0) { ssum[w * 3] = a0; ssum[w * 3 + 1] = a1; ssum[w * 3 + 2] = a2; }
    __syncthreads();
    if (t == 0) {
        float l0 = bl[0], l1 = bl[1], l2 = bl[2];
#pragma unroll
        for (int k = 0; k < 4; k++) {
            l0 += ssum[k * 3]; l1 += ssum[k * 3 + 1]; l2 += ssum[k * 3 + 2];
        }
        float mx = fmaxf(l0, fmaxf(l1, l2));
        float lse = mx + logf(expf(l0 - mx) + expf(l1 - mx) + expf(l2 - mx));
        out[g * 3 + 0] = l0 - lse;
        out[g * 3 + 1] = l1 - lse;
        out[g * 3 + 2] = l2 - lse;
    }
}

// ---------------- launcher (7 kernels) ----------------
extern "C" void kernel_launch(void* const* d_in, const int* in_sizes, int n_in,
                              void* d_out, int out_size) {
    const float* x   = (const float*)d_in[0];
    const void*  ei  = d_in[1];
    const void*  bi  = d_in[2];
    const float* W1  = (const float*)d_in[3];
    const float* b1  = (const float*)d_in[4];
    const float* g1  = (const float*)d_in[5];
    const float* be1 = (const float*)d_in[6];
    const float* W2  = (const float*)d_in[7];
    const float* b2  = (const float*)d_in[8];
    const float* g2  = (const float*)d_in[9];
    const float* be2 = (const float*)d_in[10];
    const float* W3  = (const float*)d_in[11];
    const float* b3  = (const float*)d_in[12];
    const float* g3  = (const float*)d_in[13];
    const float* be3 = (const float*)d_in[14];
    const float* Wl  = (const float*)d_in[15];
    const float* bl  = (const float*)d_in[16];
    float* out = (float*)d_out;

    const int T = 256;
    const int EB = (NE + T - 1) / T;
    const int G  = 1184;                     // 8 blocks/SM -> 64 warps (full occ)
    const int L1B = (NN * 2 + T - 1) / T;    // 2 threads per node

    k_prep<<<NBLK, T>>>(ei, bi);
    k_countbounds<<<EB, T>>>(ei, bi);
    k_scanfill<<<NBLK, T>>>(ei);
    k_l1<<<L1B, T>>>(x, W1, b1, g1, be1);
    k_l2<<<G, T>>>(W2, b2, g2, be2);
    k_l3<<<G, T>>>(W3, b3, g3, be3);
    k_poolhead<<<NG, 128>>>(Wl, bl, out);
}

// round 13
// speedup vs baseline: 1.0388x; 1.0388x over previous
#include <cuda_runtime.h>
#include <cuda_fp16.h>
#include <math_constants.h>

// ---------------- problem constants ----------------
#define NN 100000      // nodes
#define NE 3200000     // edges
#define NG 512         // graphs
#define BN_EPS 1e-5f
#define NBLK ((NN + 255) / 256)   // 391

typedef unsigned long long ull;

// ---------------- packed f32x2 helpers ----------------
__device__ __forceinline__ ull pack2(float lo, float hi) {
    ull r; asm("mov.b64 %0, {%1, %2};" : "=l"(r) : "f"(lo), "f"(hi)); return r;
}
__device__ __forceinline__ ull dup2(float v) {
    ull r; asm("mov.b64 %0, {%1, %1};" : "=l"(r) : "f"(v)); return r;
}
__device__ __forceinline__ void unpack2(ull v, float& lo, float& hi) {
    asm("mov.b64 {%0, %1}, %2;" : "=f"(lo), "=f"(hi) : "l"(v));
}
__device__ __forceinline__ void ffma2(ull& d, ull a, ull b) {
    asm("fma.rn.f32x2 %0, %1, %2, %0;" : "+l"(d) : "l"(a), "l"(b));
}

// ---------------- device scratch (no allocs allowed) ----------------
__device__ int    d_cnt[NN];
__device__ int    d_rowptr[NN + 1];
__device__ int    d_wp[NN];
__device__ ull    d_tile[512];            // lookback scan state
__device__ float2 d_csr[NE];              // (src as int bits, dis[src])
__device__ float  d_dis[NN];
__device__ float  d_y1 [(size_t)NN * 8];
__device__ __half d_y2h[(size_t)NN * 32];   // fp16 activations (64B rows)
__device__ __half d_y3h[(size_t)NN * 128];  // fp16 activations (256B rows)
__device__ float  d_stats[256];
__device__ float  d_scale[128];
__device__ float  d_shift[128];
__device__ int    d_gstart[NG];
__device__ int    d_gend[NG];
__device__ int    d_is64_edge;
__device__ int    d_is64_batch;
__device__ int    d_tick;
__device__ int    d_bar;

// ---------------- BN finalize epilogue ----------------
__device__ __forceinline__ void bn_finalize(int FO, const float* gam, const float* bet) {
    __threadfence();
    __shared__ int isLast;
    if (threadIdx.x == 0) isLast = (atomicAdd(&d_tick, 1) == (int)gridDim.x - 1);
    __syncthreads();
    if (isLast) {
        if ((int)threadIdx.x < FO) {
            int c = threadIdx.x;
            float sum = atomicAdd(&d_stats[c], 0.f);
            float sq  = atomicAdd(&d_stats[128 + c], 0.f);
            float m   = sum * (1.0f / NN);
            float var = sq * (1.0f / NN) - m * m;
            float scv = gam[c] * rsqrtf(var + BN_EPS);
            d_scale[c] = scv;
            d_shift[c] = bet[c] - m * scv;
            d_stats[c] = 0.f;
            d_stats[128 + c] = 0.f;
        }
        if (threadIdx.x == 0) d_tick = 0;
    }
}

// ---------------- prep: zero state + dtype detection ----------------
__global__ void k_prep(const void* ei, const void* bi) {
    int i = blockIdx.x * blockDim.x + threadIdx.x;
    if (i < NN) d_cnt[i] = 0;
    if (i < 512) d_tile[i] = 0ULL;
    if (i < 256) d_stats[i] = 0.f;
    if (i == 0) { d_tick = 0; d_bar = 0; }
    if (blockIdx.x == 0) {
        long long v = ((const long long*)ei)[(size_t)threadIdx.x * 6000];
        int ok = (v >= 0 && v < NN);
        ok = __syncthreads_and(ok);
        if (threadIdx.x == 0) d_is64_edge = ok;
    } else if (blockIdx.x == 1) {
        long long v = ((const long long*)bi)[(size_t)threadIdx.x * 195];
        int ok = (v >= 0 && v < NG);
        ok = __syncthreads_and(ok);
        if (threadIdx.x == 0) d_is64_batch = ok;
    }
}

// ---------------- count in-degrees + graph boundaries ----------------
__global__ void k_countbounds(const void* ei, const void* bi) {
    int e = blockIdx.x * blockDim.x + threadIdx.x;
    if (e < NE) {
        int d;
        if (d_is64_edge) d = (int)((const long long*)ei)[(size_t)NE + e];
        else             d = ((const int*)ei)[NE + e];
        atomicAdd(&d_cnt[d], 1);
    }
    if (e < NN) {
        int i = e, g, gp, gn;
        if (d_is64_batch) {
            const long long* p = (const long long*)bi;
            g  = (int)p[i];
            gp = (i > 0)      ? (int)p[i - 1] : -1;
            gn = (i < NN - 1) ? (int)p[i + 1] : NG;
        } else {
            const int* p = (const int*)bi;
            g  = p[i];
            gp = (i > 0)      ? p[i - 1] : -1;
            gn = (i < NN - 1) ? p[i + 1] : NG;
        }
        if (g != gp) d_gstart[g] = i;
        if (g != gn) d_gend[g] = i + 1;
    }
}

// ---------------- scan (lookback) + grid barrier + CSR fill, one kernel ----------------
__global__ void k_scanfill(const void* ei) {
    __shared__ int s[256];
    __shared__ int sExcl;
    int b = blockIdx.x, t = threadIdx.x;
    int i = b * 256 + t;
    int orig = (i < NN) ? d_cnt[i] : 0;
    s[t] = orig;
    __syncthreads();
    for (int o = 1; o < 256; o <<= 1) {
        int u = (t >= o) ? s[t - o] : 0;
        __syncthreads();
        s[t] += u;
        __syncthreads();
    }
    int incl = s[t];
    int agg  = s[255];
    if (t == 0) {
        if (b == 0) {
            sExcl = 0;
            *(volatile ull*)&d_tile[0] = (2ULL << 32) | (unsigned)agg;
        } else {
            *(volatile ull*)&d_tile[b] = (1ULL << 32) | (unsigned)agg;
            int excl = 0, p = b - 1;
            while (1) {
                ull v;
                do { v = *(volatile ull*)&d_tile[p]; } while ((unsigned)(v >> 32) == 0u);
                excl += (int)(unsigned)v;
                if ((unsigned)(v >> 32) == 2u) break;
                p--;
            }
            *(volatile ull*)&d_tile[b] = (2ULL << 32) | (unsigned)(excl + agg);
            sExcl = excl;
        }
    }
    __syncthreads();
    int ex = sExcl + incl - orig;
    if (i < NN) {
        d_rowptr[i] = ex;
        d_wp[i] = ex;
        d_dis[i] = rsqrtf((float)(orig + 1));
    }
    if (i == 0) d_rowptr[NN] = NE;
    // ---- grid barrier (all 391 blocks co-resident) ----
    __threadfence();
    __syncthreads();
    if (t == 0) {
        atomicAdd(&d_bar, 1);
        while (*(volatile int*)&d_bar < (int)gridDim.x) {}
    }
    __syncthreads();
    __threadfence();
    // ---- fill ----
    int stride = gridDim.x * blockDim.x;
    for (int e = b * 256 + t; e < NE; e += stride) {
        int sN, dN;
        if (d_is64_edge) {
            const long long* p = (const long long*)ei;
            sN = (int)p[e];
            dN = (int)p[(size_t)NE + e];
        } else {
            const int* p = (const int*)ei;
            sN = p[e];
            dN = p[NE + e];
        }
        int pos = atomicAdd(&d_wp[dN], 1);
        d_csr[pos] = make_float2(__int_as_float(sN), d_dis[sN]);
    }
}

// ---------------- layer 1: agg(F=2) 2-threads/node + GEMM 2->8 + relu + BN stats ----------------
__global__ void k_l1(const float* __restrict__ x,
                     const float* __restrict__ W1, const float* __restrict__ b1,
                     const float* __restrict__ g1, const float* __restrict__ be1) {
    __shared__ float sW[16], sb[8], sst[32];
    if (threadIdx.x < 16) sW[threadIdx.x] = W1[threadIdx.x];
    if (threadIdx.x < 8)  sb[threadIdx.x] = b1[threadIdx.x];
    if (threadIdx.x < 32) sst[threadIdx.x] = 0.f;
    __syncthreads();
    int gid = blockIdx.x * blockDim.x + threadIdx.x;
    int i   = gid >> 1;
    int sub = gid & 1;
    bool act = i < NN;
    float ax = 0.f, ay = 0.f, di = 0.f;
    int e = 0, end = 0;
    if (act) {
        di = d_dis[i];
        int beg = d_rowptr[i];
        end = d_rowptr[i + 1];
        e = beg + sub;
        if (sub == 0) {
            const float2 self = ((const float2*)x)[i];
            ax = self.x * di;
            ay = self.y * di;
        }
    }
    const float2* x2 = (const float2*)x;
    for (; e + 6 < end; e += 8) {
        float2 p0 = __ldg(&d_csr[e]),     p1 = __ldg(&d_csr[e + 2]);
        float2 p2 = __ldg(&d_csr[e + 4]), p3 = __ldg(&d_csr[e + 6]);
        float2 v0 = __ldg(&x2[__float_as_int(p0.x)]);
        float2 v1 = __ldg(&x2[__float_as_int(p1.x)]);
        float2 v2 = __ldg(&x2[__float_as_int(p2.x)]);
        float2 v3 = __ldg(&x2[__float_as_int(p3.x)]);
        ax += v0.x * p0.y + v1.x * p1.y + v2.x * p2.y + v3.x * p3.y;
        ay += v0.y * p0.y + v1.y * p1.y + v2.y * p2.y + v3.y * p3.y;
    }
    for (; e < end; e += 2) {
        float2 p = __ldg(&d_csr[e]);
        float2 v = __ldg(&x2[__float_as_int(p.x)]);
        ax += v.x * p.y;
        ay += v.y * p.y;
    }
    ax += __shfl_xor_sync(0xFFFFFFFFu, ax, 1);
    ay += __shfl_xor_sync(0xFFFFFFFFu, ay, 1);
    float o[8];
#pragma unroll
    for (int k = 0; k < 8; k++) o[k] = 0.f;
    if (act && sub == 0) {
        ax *= di; ay *= di;
#pragma unroll
        for (int k = 0; k < 8; k++)
            o[k] = fmaxf(fmaf(ax, sW[k], fmaf(ay, sW[8 + k], sb[k])), 0.f);
        float4* yo = (float4*)(d_y1 + (size_t)i * 8);
        yo[0] = make_float4(o[0], o[1], o[2], o[3]);
        yo[1] = make_float4(o[4], o[5], o[6], o[7]);
    }
#pragma unroll
    for (int k = 0; k < 8; k++) {
        float s = o[k], q = o[k] * o[k];
#pragma unroll
        for (int off = 16; off; off >>= 1) {
            s += __shfl_xor_sync(0xFFFFFFFFu, s, off);
            q += __shfl_xor_sync(0xFFFFFFFFu, q, off);
        }
        if ((threadIdx.x & 31) == 0) {
            atomicAdd(&sst[k], s);
            atomicAdd(&sst[16 + k], q);
        }
    }
    __syncthreads();
    if (threadIdx.x < 8) {
        atomicAdd(&d_stats[threadIdx.x], sst[threadIdx.x]);
        atomicAdd(&d_stats[128 + threadIdx.x], sst[16 + threadIdx.x]);
    }
    bn_finalize(8, g1, be1);
}

// ---------------- layer 2: agg(F=8, BN folded) + GEMM 8->32 + relu + BN stats ----------------
// output y2 stored as fp16 (64B rows) for cheap layer-3 gathers
__global__ void k_l2(const float* __restrict__ W2, const float* __restrict__ b2,
                     const float* __restrict__ g2, const float* __restrict__ be2) {
    __shared__ float sW[8 * 32], sb[32], sst[64];
    for (int k = threadIdx.x; k < 256; k += blockDim.x) sW[k] = W2[k];
    if (threadIdx.x < 32) sb[threadIdx.x] = b2[threadIdx.x];
    if (threadIdx.x < 64) sst[threadIdx.x] = 0.f;
    __syncthreads();
    int lane = threadIdx.x & 31;
    int sub  = lane >> 3;
    int ln   = lane & 7;
    int gwarp  = (blockIdx.x * blockDim.x + threadIdx.x) >> 5;
    int nwarps = (gridDim.x * blockDim.x) >> 5;
    float sc = d_scale[ln], sh = d_shift[ln];
    float ls0 = 0.f, ls1 = 0.f, ls2 = 0.f, ls3 = 0.f;
    float lq0 = 0.f, lq1 = 0.f, lq2 = 0.f, lq3 = 0.f;
    for (int n0 = gwarp * 4; n0 < NN; n0 += nwarps * 4) {
        int node = n0 + sub;
        bool act = node < NN;
        int e = 0, end = 0;
        float acc0 = 0.f, acc1 = 0.f, di = 0.f;
        if (act) {
            di = d_dis[node];
            e = d_rowptr[node];
            end = d_rowptr[node + 1];
            acc0 = fmaf(d_y1[(size_t)node * 8 + ln], sc, sh) * di;
        }
        for (; e + 8 <= end; e += 8) {
            float2 p0 = __ldg(&d_csr[e]),     p1 = __ldg(&d_csr[e + 1]);
            float2 p2 = __ldg(&d_csr[e + 2]), p3 = __ldg(&d_csr[e + 3]);
            float2 p4 = __ldg(&d_csr[e + 4]), p5 = __ldg(&d_csr[e + 5]);
            float2 p6 = __ldg(&d_csr[e + 6]), p7 = __ldg(&d_csr[e + 7]);
            float h0 = __ldg(&d_y1[(size_t)__float_as_int(p0.x) * 8 + ln]);
            float h1 = __ldg(&d_y1[(size_t)__float_as_int(p1.x) * 8 + ln]);
            float h2 = __ldg(&d_y1[(size_t)__float_as_int(p2.x) * 8 + ln]);
            float h3 = __ldg(&d_y1[(size_t)__float_as_int(p3.x) * 8 + ln]);
            float h4 = __ldg(&d_y1[(size_t)__float_as_int(p4.x) * 8 + ln]);
            float h5 = __ldg(&d_y1[(size_t)__float_as_int(p5.x) * 8 + ln]);
            float h6 = __ldg(&d_y1[(size_t)__float_as_int(p6.x) * 8 + ln]);
            float h7 = __ldg(&d_y1[(size_t)__float_as_int(p7.x) * 8 + ln]);
            acc0 = fmaf(fmaf(h0, sc, sh), p0.y, acc0);
            acc1 = fmaf(fmaf(h1, sc, sh), p1.y, acc1);
            acc0 = fmaf(fmaf(h2, sc, sh), p2.y, acc0);
            acc1 = fmaf(fmaf(h3, sc, sh), p3.y, acc1);
            acc0 = fmaf(fmaf(h4, sc, sh), p4.y, acc0);
            acc1 = fmaf(fmaf(h5, sc, sh), p5.y, acc1);
            acc0 = fmaf(fmaf(h6, sc, sh), p6.y, acc0);
            acc1 = fmaf(fmaf(h7, sc, sh), p7.y, acc1);
        }
        for (; e < end; e++) {
            float2 p = __ldg(&d_csr[e]);
            float hv = __ldg(&d_y1[(size_t)__float_as_int(p.x) * 8 + ln]);
            acc0 = fmaf(fmaf(hv, sc, sh), p.y, acc0);
        }
        float acc = (acc0 + acc1) * di;
        float4 yv = make_float4(sb[ln * 4], sb[ln * 4 + 1], sb[ln * 4 + 2], sb[ln * 4 + 3]);
#pragma unroll
        for (int f = 0; f < 8; f++) {
            float av = __shfl_sync(0xFFFFFFFFu, acc, f, 8);
            const float* wr = &sW[f * 32 + ln * 4];
            yv.x = fmaf(av, wr[0], yv.x);
            yv.y = fmaf(av, wr[1], yv.y);
            yv.z = fmaf(av, wr[2], yv.z);
            yv.w = fmaf(av, wr[3], yv.w);
        }
        yv.x = fmaxf(yv.x, 0.f); yv.y = fmaxf(yv.y, 0.f);
        yv.z = fmaxf(yv.z, 0.f); yv.w = fmaxf(yv.w, 0.f);
        if (act) {
            __half2 h01 = __floats2half2_rn(yv.x, yv.y);
            __half2 h23 = __floats2half2_rn(yv.z, yv.w);
            uint2 pk = make_uint2(*(unsigned*)&h01, *(unsigned*)&h23);
            ((uint2*)(d_y2h + (size_t)node * 32))[ln] = pk;
            ls0 += yv.x; lq0 += yv.x * yv.x;
            ls1 += yv.y; lq1 += yv.y * yv.y;
            ls2 += yv.z; lq2 += yv.z * yv.z;
            ls3 += yv.w; lq3 += yv.w * yv.w;
        }
    }
#pragma unroll
    for (int off = 8; off <= 16; off <<= 1) {
        ls0 += __shfl_xor_sync(0xFFFFFFFFu, ls0, off);
        ls1 += __shfl_xor_sync(0xFFFFFFFFu, ls1, off);
        ls2 += __shfl_xor_sync(0xFFFFFFFFu, ls2, off);
        ls3 += __shfl_xor_sync(0xFFFFFFFFu, ls3, off);
        lq0 += __shfl_xor_sync(0xFFFFFFFFu, lq0, off);
        lq1 += __shfl_xor_sync(0xFFFFFFFFu, lq1, off);
        lq2 += __shfl_xor_sync(0xFFFFFFFFu, lq2, off);
        lq3 += __shfl_xor_sync(0xFFFFFFFFu, lq3, off);
    }
    if (lane < 8) {
        atomicAdd(&sst[ln * 4 + 0], ls0); atomicAdd(&sst[32 + ln * 4 + 0], lq0);
        atomicAdd(&sst[ln * 4 + 1], ls1); atomicAdd(&sst[32 + ln * 4 + 1], lq1);
        atomicAdd(&sst[ln * 4 + 2], ls2); atomicAdd(&sst[32 + ln * 4 + 2], lq2);
        atomicAdd(&sst[ln * 4 + 3], ls3); atomicAdd(&sst[32 + ln * 4 + 3], lq3);
    }
    __syncthreads();
    if (threadIdx.x < 32) {
        atomicAdd(&d_stats[threadIdx.x], sst[threadIdx.x]);
        atomicAdd(&d_stats[128 + threadIdx.x], sst[32 + threadIdx.x]);
    }
    bn_finalize(32, g2, be2);
}

// ---------------- layer 3: fp16 gather + GEMM 32->128 (4-node batched, f32x2) + BN stats ----------------
__global__ void k_l3(const float* __restrict__ W3, const float* __restrict__ b3,
                     const float* __restrict__ g3, const float* __restrict__ be3) {
    __shared__ ull   sW[2048];
    __shared__ float sb[128];
    __shared__ float bs[256];
    for (int k = threadIdx.x; k < 2048; k += blockDim.x)
        sW[k] = ((const ull*)W3)[k];
    if (threadIdx.x < 128) sb[threadIdx.x] = b3[threadIdx.x];
    bs[threadIdx.x] = 0.f;
    __syncthreads();
    int lane = threadIdx.x & 31;
    int gwarp  = (blockIdx.x * blockDim.x + threadIdx.x) >> 5;
    int nwarps = (gridDim.x * blockDim.x) >> 5;
    float sc = d_scale[lane], sh = d_shift[lane];
    ull bias01 = pack2(sb[lane * 4], sb[lane * 4 + 1]);
    ull bias23 = pack2(sb[lane * 4 + 2], sb[lane * 4 + 3]);
    float ls0 = 0.f, ls1 = 0.f, ls2 = 0.f, ls3 = 0.f;
    float lq0 = 0.f, lq1 = 0.f, lq2 = 0.f, lq3 = 0.f;
    for (int n0 = gwarp * 4; n0 < NN; n0 += nwarps * 4) {
        float accs[4];
#pragma unroll
        for (int nb = 0; nb < 4; nb++) {
            int node = n0 + nb;
            float acc0 = 0.f, acc1 = 0.f, di = 0.f;
            if (node < NN) {
                di = d_dis[node];
                int e = d_rowptr[node], end = d_rowptr[node + 1];
                acc0 = fmaf(__half2float(d_y2h[(size_t)node * 32 + lane]), sc, sh) * di;
                for (; e + 8 <= end; e += 8) {
                    float2 p0 = __ldg(&d_csr[e]),     p1 = __ldg(&d_csr[e + 1]);
                    float2 p2 = __ldg(&d_csr[e + 2]), p3 = __ldg(&d_csr[e + 3]);
                    float2 p4 = __ldg(&d_csr[e + 4]), p5 = __ldg(&d_csr[e + 5]);
                    float2 p6 = __ldg(&d_csr[e + 6]), p7 = __ldg(&d_csr[e + 7]);
                    float h0 = __half2float(d_y2h[(size_t)__float_as_int(p0.x) * 32 + lane]);
                    float h1 = __half2float(d_y2h[(size_t)__float_as_int(p1.x) * 32 + lane]);
                    float h2 = __half2float(d_y2h[(size_t)__float_as_int(p2.x) * 32 + lane]);
                    float h3 = __half2float(d_y2h[(size_t)__float_as_int(p3.x) * 32 + lane]);
                    float h4 = __half2float(d_y2h[(size_t)__float_as_int(p4.x) * 32 + lane]);
                    float h5 = __half2float(d_y2h[(size_t)__float_as_int(p5.x) * 32 + lane]);
                    float h6 = __half2float(d_y2h[(size_t)__float_as_int(p6.x) * 32 + lane]);
                    float h7 = __half2float(d_y2h[(size_t)__float_as_int(p7.x) * 32 + lane]);
                    acc0 = fmaf(fmaf(h0, sc, sh), p0.y, acc0);
                    acc1 = fmaf(fmaf(h1, sc, sh), p1.y, acc1);
                    acc0 = fmaf(fmaf(h2, sc, sh), p2.y, acc0);
                    acc1 = fmaf(fmaf(h3, sc, sh), p3.y, acc1);
                    acc0 = fmaf(fmaf(h4, sc, sh), p4.y, acc0);
                    acc1 = fmaf(fmaf(h5, sc, sh), p5.y, acc1);
                    acc0 = fmaf(fmaf(h6, sc, sh), p6.y, acc0);
                    acc1 = fmaf(fmaf(h7, sc, sh), p7.y, acc1);
                }
                for (; e < end; e++) {
                    float2 p = __ldg(&d_csr[e]);
                    float hv = __half2float(d_y2h[(size_t)__float_as_int(p.x) * 32 + lane]);
                    acc0 = fmaf(fmaf(hv, sc, sh), p.y, acc0);
                }
            }
            accs[nb] = (acc0 + acc1) * di;
        }
        ull a01[4], a23[4];
#pragma unroll
        for (int nb = 0; nb < 4; nb++) { a01[nb] = bias01; a23[nb] = bias23; }
#pragma unroll
        for (int f = 0; f < 32; f++) {
            ull w01 = sW[f * 64 + lane * 2];
            ull w23 = sW[f * 64 + lane * 2 + 1];
#pragma unroll
            for (int nb = 0; nb < 4; nb++) {
                ull avv = dup2(__shfl_sync(0xFFFFFFFFu, accs[nb], f));
                ffma2(a01[nb], avv, w01);
                ffma2(a23[nb], avv, w23);
            }
        }
#pragma unroll
        for (int nb = 0; nb < 4; nb++) {
            int node = n0 + nb;
            if (node >= NN) break;
            float v0, v1, v2, v3;
            unpack2(a01[nb], v0, v1);
            unpack2(a23[nb], v2, v3);
            v0 = fmaxf(v0, 0.f); v1 = fmaxf(v1, 0.f);
            v2 = fmaxf(v2, 0.f); v3 = fmaxf(v3, 0.f);
            __half2 h01 = __floats2half2_rn(v0, v1);
            __half2 h23 = __floats2half2_rn(v2, v3);
            uint2 pk = make_uint2(*(unsigned*)&h01, *(unsigned*)&h23);
            ((uint2*)(d_y3h + (size_t)node * 128))[lane] = pk;
            ls0 += v0; lq0 += v0 * v0;
            ls1 += v1; lq1 += v1 * v1;
            ls2 += v2; lq2 += v2 * v2;
            ls3 += v3; lq3 += v3 * v3;
        }
    }
    atomicAdd(&bs[lane * 4 + 0], ls0); atomicAdd(&bs[128 + lane * 4 + 0], lq0);
    atomicAdd(&bs[lane * 4 + 1], ls1); atomicAdd(&bs[128 + lane * 4 + 1], lq1);
    atomicAdd(&bs[lane * 4 + 2], ls2); atomicAdd(&bs[128 + lane * 4 + 2], lq2);
    atomicAdd(&bs[lane * 4 + 3], ls3); atomicAdd(&bs[128 + lane * 4 + 3], lq3);
    __syncthreads();
    atomicAdd(&d_stats[threadIdx.x], bs[threadIdx.x]);
    bn_finalize(128, g3, be3);
}

// ---------------- fused max-pool (BN folded, fp16 reads) + linear + log_softmax ----------------
__global__ void k_poolhead(const float* __restrict__ Wl, const float* __restrict__ bl,
                           float* __restrict__ out) {
    __shared__ float ssum[12];
    int g = blockIdx.x, t = threadIdx.x;
    float sc = d_scale[t], sh = d_shift[t];
    float m = -CUDART_INF_F;
    int s = d_gstart[g], e = d_gend[g];
    int i = s;
    for (; i + 4 <= e; i += 4) {
        float v0 = __half2float(d_y3h[(size_t)(i + 0) * 128 + t]);
        float v1 = __half2float(d_y3h[(size_t)(i + 1) * 128 + t]);
        float v2 = __half2float(d_y3h[(size_t)(i + 2) * 128 + t]);
        float v3 = __half2float(d_y3h[(size_t)(i + 3) * 128 + t]);
        m = fmaxf(m, fmaxf(fmaxf(v0, v1), fmaxf(v2, v3)));
    }
    for (; i < e; i++) m = fmaxf(m, __half2float(d_y3h[(size_t)i * 128 + t]));
    float p = fmaf(m, sc, sh);
    float a0 = p * Wl[t * 3 + 0];
    float a1 = p * Wl[t * 3 + 1];
    float a2 = p * Wl[t * 3 + 2];
#pragma unroll
    for (int o = 16; o > 0; o >>= 1) {
        a0 += __shfl_down_sync(0xFFFFFFFFu, a0, o);
        a1 += __shfl_down_sync(0xFFFFFFFFu, a1, o);
        a2 += __shfl_down_sync(0xFFFFFFFFu, a2, o);
    }
    int w = t >> 5;
    if ((t & 31) == 0) { ssum[w * 3] = a0; ssum[w * 3 + 1] = a1; ssum[w * 3 + 2] = a2; }
    __syncthreads();
    if (t == 0) {
        float l0 = bl[0], l1 = bl[1], l2 = bl[2];
#pragma unroll
        for (int k = 0; k < 4; k++) {
            l0 += ssum[k * 3]; l1 += ssum[k * 3 + 1]; l2 += ssum[k * 3 + 2];
        }
        float mx = fmaxf(l0, fmaxf(l1, l2));
        float lse = mx + logf(expf(l0 - mx) + expf(l1 - mx) + expf(l2 - mx));
        out[g * 3 + 0] = l0 - lse;
        out[g * 3 + 1] = l1 - lse;
        out[g * 3 + 2] = l2 - lse;
    }
}

// ---------------- launcher (7 kernels) ----------------
extern "C" void kernel_launch(void* const* d_in, const int* in_sizes, int n_in,
                              void* d_out, int out_size) {
    const float* x   = (const float*)d_in[0];
    const void*  ei  = d_in[1];
    const void*  bi  = d_in[2];
    const float* W1  = (const float*)d_in[3];
    const float* b1  = (const float*)d_in[4];
    const float* g1  = (const float*)d_in[5];
    const float* be1 = (const float*)d_in[6];
    const float* W2  = (const float*)d_in[7];
    const float* b2  = (const float*)d_in[8];
    const float* g2  = (const float*)d_in[9];
    const float* be2 = (const float*)d_in[10];
    const float* W3  = (const float*)d_in[11];
    const float* b3  = (const float*)d_in[12];
    const float* g3  = (const float*)d_in[13];
    const float* be3 = (const float*)d_in[14];
    const float* Wl  = (const float*)d_in[15];
    const float* bl  = (const float*)d_in[16];
    float* out = (float*)d_out;

    const int T = 256;
    const int EB = (NE + T - 1) / T;
    const int G  = 1184;
    const int L1B = (NN * 2 + T - 1) / T;

    k_prep<<<NBLK, T>>>(ei, bi);
    k_countbounds<<<EB, T>>>(ei, bi);
    k_scanfill<<<NBLK, T>>>(ei);
    k_l1<<<L1B, T>>>(x, W1, b1, g1, be1);
    k_l2<<<G, T>>>(W2, b2, g2, be2);
    k_l3<<<G, T>>>(W3, b3, g3, be3);
    k_poolhead<<<NG, 128>>>(Wl, bl, out);
}

// round 14
// speedup vs baseline: 1.0611x; 1.0214x over previous
#include <cuda_runtime.h>
#include <cuda_fp16.h>
#include <math_constants.h>

// ---------------- problem constants ----------------
#define NN 100000      // nodes
#define NE 3200000     // edges
#define NG 512         // graphs
#define BN_EPS 1e-5f
#define NBLK ((NN + 255) / 256)   // 391

typedef unsigned long long ull;

// ---------------- packed f32x2 helpers ----------------
__device__ __forceinline__ ull pack2(float lo, float hi) {
    ull r; asm("mov.b64 %0, {%1, %2};" : "=l"(r) : "f"(lo), "f"(hi)); return r;
}
__device__ __forceinline__ ull dup2(float v) {
    ull r; asm("mov.b64 %0, {%1, %1};" : "=l"(r) : "f"(v)); return r;
}
__device__ __forceinline__ void unpack2(ull v, float& lo, float& hi) {
    asm("mov.b64 {%0, %1}, %2;" : "=f"(lo), "=f"(hi) : "l"(v));
}
__device__ __forceinline__ void ffma2(ull& d, ull a, ull b) {
    asm("fma.rn.f32x2 %0, %1, %2, %0;" : "+l"(d) : "l"(a), "l"(b));
}

// ---------------- device scratch (no allocs allowed) ----------------
__device__ int    d_cnt[NN];
__device__ int    d_rowptr[NN + 1];
__device__ int    d_wp[NN];
__device__ ull    d_tile[512];              // lookback scan state
__device__ int    d_csr[NE];                // src index only (4B/edge)
__device__ float  d_dis[NN];
__device__ float4 d_z[NN];                  // (x0*dis, x1*dis, dis, 0)
__device__ float  d_T[NN];                  // dis_i + sum_{s in N(i)} dis_s
__device__ float  d_u1[(size_t)NN * 8];     // y1 * dis (fp32)
__device__ __half d_u2h[(size_t)NN * 32];   // y2 * dis (fp16, 64B rows)
__device__ __half d_y3h[(size_t)NN * 128];  // raw y3 (fp16)
__device__ float  d_stats[256];
__device__ float  d_scale[128];
__device__ float  d_shift[128];
__device__ int    d_gstart[NG];
__device__ int    d_gend[NG];
__device__ int    d_is64_edge;
__device__ int    d_is64_batch;
__device__ int    d_tick;
__device__ int    d_bar;    // scanfill barrier (zeroed by prepcount)
__device__ int    d_bar2;   // prepcount barrier (zeroed by previous poolhead; static 0 first run)

// ---------------- BN finalize epilogue ----------------
__device__ __forceinline__ void bn_finalize(int FO, const float* gam, const float* bet) {
    __threadfence();
    __shared__ int isLast;
    if (threadIdx.x == 0) isLast = (atomicAdd(&d_tick, 1) == (int)gridDim.x - 1);
    __syncthreads();
    if (isLast) {
        if ((int)threadIdx.x < FO) {
            int c = threadIdx.x;
            float sum = atomicAdd(&d_stats[c], 0.f);
            float sq  = atomicAdd(&d_stats[128 + c], 0.f);
            float m   = sum * (1.0f / NN);
            float var = sq * (1.0f / NN) - m * m;
            float scv = gam[c] * rsqrtf(var + BN_EPS);
            d_scale[c] = scv;
            d_shift[c] = bet[c] - m * scv;
            d_stats[c] = 0.f;
            d_stats[128 + c] = 0.f;
        }
        if (threadIdx.x == 0) d_tick = 0;
    }
}

// ---------------- prep (zero + detect) + grid barrier + count/bounds ----------------
__global__ void k_prepcount(const void* ei, const void* bi) {
    int i = blockIdx.x * blockDim.x + threadIdx.x;
    if (i < NN) d_cnt[i] = 0;
    if (i < 512) d_tile[i] = 0ULL;
    if (i < 256) d_stats[i] = 0.f;
    if (i == 0) { d_tick = 0; d_bar = 0; }
    if (blockIdx.x == 0) {
        long long v = ((const long long*)ei)[(size_t)threadIdx.x * 6000];
        int ok = (v >= 0 && v < NN);
        ok = __syncthreads_and(ok);
        if (threadIdx.x == 0) d_is64_edge = ok;
    } else if (blockIdx.x == 1) {
        long long v = ((const long long*)bi)[(size_t)threadIdx.x * 195];
        int ok = (v >= 0 && v < NG);
        ok = __syncthreads_and(ok);
        if (threadIdx.x == 0) d_is64_batch = ok;
    }
    // grid barrier (391 blocks co-resident; d_bar2 zeroed by prior replay's poolhead)
    __threadfence();
    __syncthreads();
    if (threadIdx.x == 0) {
        atomicAdd(&d_bar2, 1);
        while (*(volatile int*)&d_bar2 < (int)gridDim.x) {}
    }
    __syncthreads();
    __threadfence();
    // count in-degrees (grid-stride) + graph boundaries
    int e64 = d_is64_edge, b64 = d_is64_batch;
    int stride = gridDim.x * blockDim.x;
    for (int e = i; e < NE; e += stride) {
        int d;
        if (e64) d = (int)((const long long*)ei)[(size_t)NE + e];
        else     d = ((const int*)ei)[NE + e];
        atomicAdd(&d_cnt[d], 1);
    }
    if (i < NN) {
        int g, gp, gn;
        if (b64) {
            const long long* p = (const long long*)bi;
            g  = (int)p[i];
            gp = (i > 0)      ? (int)p[i - 1] : -1;
            gn = (i < NN - 1) ? (int)p[i + 1] : NG;
        } else {
            const int* p = (const int*)bi;
            g  = p[i];
            gp = (i > 0)      ? p[i - 1] : -1;
            gn = (i < NN - 1) ? p[i + 1] : NG;
        }
        if (g != gp) d_gstart[g] = i;
        if (g != gn) d_gend[g] = i + 1;
    }
}

// ---------------- scan (lookback) + grid barrier + z build + CSR fill ----------------
__global__ void k_scanfill(const void* ei, const float* __restrict__ x) {
    __shared__ int s[256];
    __shared__ int sExcl;
    int b = blockIdx.x, t = threadIdx.x;
    int i = b * 256 + t;
    int orig = (i < NN) ? d_cnt[i] : 0;
    s[t] = orig;
    __syncthreads();
    for (int o = 1; o < 256; o <<= 1) {
        int u = (t >= o) ? s[t - o] : 0;
        __syncthreads();
        s[t] += u;
        __syncthreads();
    }
    int incl = s[t];
    int agg  = s[255];
    if (t == 0) {
        if (b == 0) {
            sExcl = 0;
            *(volatile ull*)&d_tile[0] = (2ULL << 32) | (unsigned)agg;
        } else {
            *(volatile ull*)&d_tile[b] = (1ULL << 32) | (unsigned)agg;
            int excl = 0, p = b - 1;
            while (1) {
                ull v;
                do { v = *(volatile ull*)&d_tile[p]; } while ((unsigned)(v >> 32) == 0u);
                excl += (int)(unsigned)v;
                if ((unsigned)(v >> 32) == 2u) break;
                p--;
            }
            *(volatile ull*)&d_tile[b] = (2ULL << 32) | (unsigned)(excl + agg);
            sExcl = excl;
        }
    }
    __syncthreads();
    int ex = sExcl + incl - orig;
    float di_reg = rsqrtf((float)(orig + 1));
    if (i < NN) {
        d_rowptr[i] = ex;
        d_wp[i] = ex;
        d_dis[i] = di_reg;
        float2 xv = ((const float2*)x)[i];
        d_z[i] = make_float4(xv.x * di_reg, xv.y * di_reg, di_reg, 0.f);
    }
    if (i == 0) d_rowptr[NN] = NE;
    // ---- grid barrier ----
    __threadfence();
    __syncthreads();
    if (t == 0) {
        atomicAdd(&d_bar, 1);
        while (*(volatile int*)&d_bar < (int)gridDim.x) {}
    }
    __syncthreads();
    __threadfence();
    // ---- fill: csr entry = src index only ----
    int stride = gridDim.x * blockDim.x;
    for (int e = b * 256 + t; e < NE; e += stride) {
        int sN, dN;
        if (d_is64_edge) {
            const long long* p = (const long long*)ei;
            sN = (int)p[e];
            dN = (int)p[(size_t)NE + e];
        } else {
            const int* p = (const int*)ei;
            sN = p[e];
            dN = p[NE + e];
        }
        int pos = atomicAdd(&d_wp[dN], 1);
        d_csr[pos] = sN;
    }
}

// ---------------- layer 1: agg(z) 2-threads/node + GEMM 2->8 + relu + T + BN stats ----------------
__global__ void k_l1(const float* __restrict__ W1, const float* __restrict__ b1,
                     const float* __restrict__ g1, const float* __restrict__ be1) {
    __shared__ float sW[16], sb[8], sst[32];
    if (threadIdx.x < 16) sW[threadIdx.x] = W1[threadIdx.x];
    if (threadIdx.x < 8)  sb[threadIdx.x] = b1[threadIdx.x];
    if (threadIdx.x < 32) sst[threadIdx.x] = 0.f;
    __syncthreads();
    int gid = blockIdx.x * blockDim.x + threadIdx.x;
    int i   = gid >> 1;
    int sub = gid & 1;
    bool act = i < NN;
    float ax = 0.f, ay = 0.f, S = 0.f, di = 0.f;
    int e = 0, end = 0;
    if (act) {
        int beg = d_rowptr[i];
        end = d_rowptr[i + 1];
        e = beg + sub;
        if (sub == 0) {
            float4 zi = d_z[i];
            ax = zi.x;               // = x0 * dis_i  (self term)
            ay = zi.y;
            di = zi.z;
        }
    }
    for (; e + 6 < end; e += 8) {     // 4 edges per thread per iter (stride 2)
        int c0 = __ldg(&d_csr[e]),     c1 = __ldg(&d_csr[e + 2]);
        int c2 = __ldg(&d_csr[e + 4]), c3 = __ldg(&d_csr[e + 6]);
        float4 z0 = __ldg(&d_z[c0]);
        float4 z1 = __ldg(&d_z[c1]);
        float4 z2 = __ldg(&d_z[c2]);
        float4 z3 = __ldg(&d_z[c3]);
        ax += z0.x + z1.x + z2.x + z3.x;
        ay += z0.y + z1.y + z2.y + z3.y;
        S  += z0.z + z1.z + z2.z + z3.z;
    }
    for (; e < end; e += 2) {
        float4 z = __ldg(&d_z[__ldg(&d_csr[e])]);
        ax += z.x;
        ay += z.y;
        S  += z.z;
    }
    ax += __shfl_xor_sync(0xFFFFFFFFu, ax, 1);
    ay += __shfl_xor_sync(0xFFFFFFFFu, ay, 1);
    S  += __shfl_xor_sync(0xFFFFFFFFu, S, 1);
    float o[8];
#pragma unroll
    for (int k = 0; k < 8; k++) o[k] = 0.f;
    if (act && sub == 0) {
        d_T[i] = di + S;             // shared by layers 2 and 3
        float gx = ax * di, gy = ay * di;
#pragma unroll
        for (int k = 0; k < 8; k++)
            o[k] = fmaxf(fmaf(gx, sW[k], fmaf(gy, sW[8 + k], sb[k])), 0.f);
        float4* yo = (float4*)(d_u1 + (size_t)i * 8);
        yo[0] = make_float4(o[0] * di, o[1] * di, o[2] * di, o[3] * di);
        yo[1] = make_float4(o[4] * di, o[5] * di, o[6] * di, o[7] * di);
    }
#pragma unroll
    for (int k = 0; k < 8; k++) {
        float s = o[k], q = o[k] * o[k];   // stats on RAW y1
#pragma unroll
        for (int off = 16; off; off >>= 1) {
            s += __shfl_xor_sync(0xFFFFFFFFu, s, off);
            q += __shfl_xor_sync(0xFFFFFFFFu, q, off);
        }
        if ((threadIdx.x & 31) == 0) {
            atomicAdd(&sst[k], s);
            atomicAdd(&sst[16 + k], q);
        }
    }
    __syncthreads();
    if (threadIdx.x < 8) {
        atomicAdd(&d_stats[threadIdx.x], sst[threadIdx.x]);
        atomicAdd(&d_stats[128 + threadIdx.x], sst[16 + threadIdx.x]);
    }
    bn_finalize(8, g1, be1);
}

// ---------------- layer 2: plain-sum agg + GEMM 8->32 + relu + BN stats ----------------
__global__ void k_l2(const float* __restrict__ W2, const float* __restrict__ b2,
                     const float* __restrict__ g2, const float* __restrict__ be2) {
    __shared__ float sW[8 * 32], sb[32], sst[64];
    for (int k = threadIdx.x; k < 256; k += blockDim.x) sW[k] = W2[k];
    if (threadIdx.x < 32) sb[threadIdx.x] = b2[threadIdx.x];
    if (threadIdx.x < 64) sst[threadIdx.x] = 0.f;
    __syncthreads();
    int lane = threadIdx.x & 31;
    int sub  = lane >> 3;
    int ln   = lane & 7;
    int gwarp  = (blockIdx.x * blockDim.x + threadIdx.x) >> 5;
    int nwarps = (gridDim.x * blockDim.x) >> 5;
    float sc = d_scale[ln], sh = d_shift[ln];
    float ls0 = 0.f, ls1 = 0.f, ls2 = 0.f, ls3 = 0.f;
    float lq0 = 0.f, lq1 = 0.f, lq2 = 0.f, lq3 = 0.f;
    for (int n0 = gwarp * 4; n0 < NN; n0 += nwarps * 4) {
        int node = n0 + sub;
        bool act = node < NN;
        int e = 0, end = 0;
        float acc0 = 0.f, acc1 = 0.f, di = 0.f, Tv = 0.f;
        if (act) {
            di = d_dis[node];
            Tv = d_T[node];
            e = d_rowptr[node];
            end = d_rowptr[node + 1];
            acc0 = d_u1[(size_t)node * 8 + ln];   // self (u already has dis folded)
        }
        for (; e + 8 <= end; e += 8) {
            int c0 = __ldg(&d_csr[e]),     c1 = __ldg(&d_csr[e + 1]);
            int c2 = __ldg(&d_csr[e + 2]), c3 = __ldg(&d_csr[e + 3]);
            int c4 = __ldg(&d_csr[e + 4]), c5 = __ldg(&d_csr[e + 5]);
            int c6 = __ldg(&d_csr[e + 6]), c7 = __ldg(&d_csr[e + 7]);
            float h0 = __ldg(&d_u1[(size_t)c0 * 8 + ln]);
            float h1 = __ldg(&d_u1[(size_t)c1 * 8 + ln]);
            float h2 = __ldg(&d_u1[(size_t)c2 * 8 + ln]);
            float h3 = __ldg(&d_u1[(size_t)c3 * 8 + ln]);
            float h4 = __ldg(&d_u1[(size_t)c4 * 8 + ln]);
            float h5 = __ldg(&d_u1[(size_t)c5 * 8 + ln]);
            float h6 = __ldg(&d_u1[(size_t)c6 * 8 + ln]);
            float h7 = __ldg(&d_u1[(size_t)c7 * 8 + ln]);
            acc0 += (h0 + h2) + (h4 + h6);
            acc1 += (h1 + h3) + (h5 + h7);
        }
        for (; e < end; e++) {
            acc0 += __ldg(&d_u1[(size_t)__ldg(&d_csr[e]) * 8 + ln]);
        }
        float U = acc0 + acc1;
        float aggc = di * fmaf(sc, U, sh * Tv);
        float4 yv = make_float4(sb[ln * 4], sb[ln * 4 + 1], sb[ln * 4 + 2], sb[ln * 4 + 3]);
#pragma unroll
        for (int f = 0; f < 8; f++) {
            float av = __shfl_sync(0xFFFFFFFFu, aggc, f, 8);
            const float* wr = &sW[f * 32 + ln * 4];
            yv.x = fmaf(av, wr[0], yv.x);
            yv.y = fmaf(av, wr[1], yv.y);
            yv.z = fmaf(av, wr[2], yv.z);
            yv.w = fmaf(av, wr[3], yv.w);
        }
        yv.x = fmaxf(yv.x, 0.f); yv.y = fmaxf(yv.y, 0.f);
        yv.z = fmaxf(yv.z, 0.f); yv.w = fmaxf(yv.w, 0.f);
        if (act) {
            __half2 h01 = __floats2half2_rn(yv.x * di, yv.y * di);   // store u2 = y2*dis
            __half2 h23 = __floats2half2_rn(yv.z * di, yv.w * di);
            uint2 pk = make_uint2(*(unsigned*)&h01, *(unsigned*)&h23);
            ((uint2*)(d_u2h + (size_t)node * 32))[ln] = pk;
            ls0 += yv.x; lq0 += yv.x * yv.x;                          // stats on RAW y2
            ls1 += yv.y; lq1 += yv.y * yv.y;
            ls2 += yv.z; lq2 += yv.z * yv.z;
            ls3 += yv.w; lq3 += yv.w * yv.w;
        }
    }
#pragma unroll
    for (int off = 8; off <= 16; off <<= 1) {
        ls0 += __shfl_xor_sync(0xFFFFFFFFu, ls0, off);
        ls1 += __shfl_xor_sync(0xFFFFFFFFu, ls1, off);
        ls2 += __shfl_xor_sync(0xFFFFFFFFu, ls2, off);
        ls3 += __shfl_xor_sync(0xFFFFFFFFu, ls3, off);
        lq0 += __shfl_xor_sync(0xFFFFFFFFu, lq0, off);
        lq1 += __shfl_xor_sync(0xFFFFFFFFu, lq1, off);
        lq2 += __shfl_xor_sync(0xFFFFFFFFu, lq2, off);
        lq3 += __shfl_xor_sync(0xFFFFFFFFu, lq3, off);
    }
    if (lane < 8) {
        atomicAdd(&sst[ln * 4 + 0], ls0); atomicAdd(&sst[32 + ln * 4 + 0], lq0);
        atomicAdd(&sst[ln * 4 + 1], ls1); atomicAdd(&sst[32 + ln * 4 + 1], lq1);
        atomicAdd(&sst[ln * 4 + 2], ls2); atomicAdd(&sst[32 + ln * 4 + 2], lq2);
        atomicAdd(&sst[ln * 4 + 3], ls3); atomicAdd(&sst[32 + ln * 4 + 3], lq3);
    }
    __syncthreads();
    if (threadIdx.x < 32) {
        atomicAdd(&d_stats[threadIdx.x], sst[threadIdx.x]);
        atomicAdd(&d_stats[128 + threadIdx.x], sst[32 + threadIdx.x]);
    }
    bn_finalize(32, g2, be2);
}

// ---------------- layer 3: plain-sum fp16 agg + GEMM 32->128 (4-node, f32x2) + BN stats ----------------
__global__ void k_l3(const float* __restrict__ W3, const float* __restrict__ b3,
                     const float* __restrict__ g3, const float* __restrict__ be3) {
    __shared__ ull   sW[2048];
    __shared__ float sb[128];
    __shared__ float bs[256];
    for (int k = threadIdx.x; k < 2048; k += blockDim.x)
        sW[k] = ((const ull*)W3)[k];
    if (threadIdx.x < 128) sb[threadIdx.x] = b3[threadIdx.x];
    bs[threadIdx.x] = 0.f;
    __syncthreads();
    int lane = threadIdx.x & 31;
    int gwarp  = (blockIdx.x * blockDim.x + threadIdx.x) >> 5;
    int nwarps = (gridDim.x * blockDim.x) >> 5;
    float sc = d_scale[lane], sh = d_shift[lane];
    ull bias01 = pack2(sb[lane * 4], sb[lane * 4 + 1]);
    ull bias23 = pack2(sb[lane * 4 + 2], sb[lane * 4 + 3]);
    float ls0 = 0.f, ls1 = 0.f, ls2 = 0.f, ls3 = 0.f;
    float lq0 = 0.f, lq1 = 0.f, lq2 = 0.f, lq3 = 0.f;
    for (int n0 = gwarp * 4; n0 < NN; n0 += nwarps * 4) {
        float accs[4];
#pragma unroll
        for (int nb = 0; nb < 4; nb++) {
            int node = n0 + nb;
            float acc0 = 0.f, acc1 = 0.f, di = 0.f, Tv = 0.f;
            if (node < NN) {
                di = d_dis[node];
                Tv = d_T[node];
                int e = d_rowptr[node], end = d_rowptr[node + 1];
                acc0 = __half2float(d_u2h[(size_t)node * 32 + lane]);  // self
                for (; e + 8 <= end; e += 8) {
                    int c0 = __ldg(&d_csr[e]),     c1 = __ldg(&d_csr[e + 1]);
                    int c2 = __ldg(&d_csr[e + 2]), c3 = __ldg(&d_csr[e + 3]);
                    int c4 = __ldg(&d_csr[e + 4]), c5 = __ldg(&d_csr[e + 5]);
                    int c6 = __ldg(&d_csr[e + 6]), c7 = __ldg(&d_csr[e + 7]);
                    float h0 = __half2float(d_u2h[(size_t)c0 * 32 + lane]);
                    float h1 = __half2float(d_u2h[(size_t)c1 * 32 + lane]);
                    float h2 = __half2float(d_u2h[(size_t)c2 * 32 + lane]);
                    float h3 = __half2float(d_u2h[(size_t)c3 * 32 + lane]);
                    float h4 = __half2float(d_u2h[(size_t)c4 * 32 + lane]);
                    float h5 = __half2float(d_u2h[(size_t)c5 * 32 + lane]);
                    float h6 = __half2float(d_u2h[(size_t)c6 * 32 + lane]);
                    float h7 = __half2float(d_u2h[(size_t)c7 * 32 + lane]);
                    acc0 += (h0 + h2) + (h4 + h6);
                    acc1 += (h1 + h3) + (h5 + h7);
                }
                for (; e < end; e++) {
                    acc0 += __half2float(d_u2h[(size_t)__ldg(&d_csr[e]) * 32 + lane]);
                }
            }
            float U = acc0 + acc1;
            accs[nb] = di * fmaf(sc, U, sh * Tv);
        }
        ull a01[4], a23[4];
#pragma unroll
        for (int nb = 0; nb < 4; nb++) { a01[nb] = bias01; a23[nb] = bias23; }
#pragma unroll
        for (int f = 0; f < 32; f++) {
            ull w01 = sW[f * 64 + lane * 2];
            ull w23 = sW[f * 64 + lane * 2 + 1];
#pragma unroll
            for (int nb = 0; nb < 4; nb++) {
                ull avv = dup2(__shfl_sync(0xFFFFFFFFu, accs[nb], f));
                ffma2(a01[nb], avv, w01);
                ffma2(a23[nb], avv, w23);
            }
        }
#pragma unroll
        for (int nb = 0; nb < 4; nb++) {
            int node = n0 + nb;
            if (node >= NN) break;
            float v0, v1, v2, v3;
            unpack2(a01[nb], v0, v1);
            unpack2(a23[nb], v2, v3);
            v0 = fmaxf(v0, 0.f); v1 = fmaxf(v1, 0.f);
            v2 = fmaxf(v2, 0.f); v3 = fmaxf(v3, 0.f);
            __half2 h01 = __floats2half2_rn(v0, v1);
            __half2 h23 = __floats2half2_rn(v2, v3);
            uint2 pk = make_uint2(*(unsigned*)&h01, *(unsigned*)&h23);
            ((uint2*)(d_y3h + (size_t)node * 128))[lane] = pk;
            ls0 += v0; lq0 += v0 * v0;
            ls1 += v1; lq1 += v1 * v1;
            ls2 += v2; lq2 += v2 * v2;
            ls3 += v3; lq3 += v3 * v3;
        }
    }
    atomicAdd(&bs[lane * 4 + 0], ls0); atomicAdd(&bs[128 + lane * 4 + 0], lq0);
    atomicAdd(&bs[lane * 4 + 1], ls1); atomicAdd(&bs[128 + lane * 4 + 1], lq1);
    atomicAdd(&bs[lane * 4 + 2], ls2); atomicAdd(&bs[128 + lane * 4 + 2], lq2);
    atomicAdd(&bs[lane * 4 + 3], ls3); atomicAdd(&bs[128 + lane * 4 + 3], lq3);
    __syncthreads();
    atomicAdd(&d_stats[threadIdx.x], bs[threadIdx.x]);
    bn_finalize(128, g3, be3);
}

// ---------------- fused max-pool (BN folded, fp16 reads) + linear + log_softmax ----------------
__global__ void k_poolhead(const float* __restrict__ Wl, const float* __restrict__ bl,
                           float* __restrict__ out) {
    __shared__ float ssum[12];
    int g = blockIdx.x, t = threadIdx.x;
    if (g == 0 && t == 0) d_bar2 = 0;   // reset prepcount barrier for next replay
    float sc = d_scale[t], sh = d_shift[t];
    float m = -CUDART_INF_F;
    int s = d_gstart[g], e = d_gend[g];
    int i = s;
    for (; i + 4 <= e; i += 4) {
        float v0 = __half2float(d_y3h[(size_t)(i + 0) * 128 + t]);
        float v1 = __half2float(d_y3h[(size_t)(i + 1) * 128 + t]);
        float v2 = __half2float(d_y3h[(size_t)(i + 2) * 128 + t]);
        float v3 = __half2float(d_y3h[(size_t)(i + 3) * 128 + t]);
        m = fmaxf(m, fmaxf(fmaxf(v0, v1), fmaxf(v2, v3)));
    }
    for (; i < e; i++) m = fmaxf(m, __half2float(d_y3h[(size_t)i * 128 + t]));
    float p = fmaf(m, sc, sh);
    float a0 = p * Wl[t * 3 + 0];
    float a1 = p * Wl[t * 3 + 1];
    float a2 = p * Wl[t * 3 + 2];
#pragma unroll
    for (int o = 16; o > 0; o >>= 1) {
        a0 += __shfl_down_sync(0xFFFFFFFFu, a0, o);
        a1 += __shfl_down_sync(0xFFFFFFFFu, a1, o);
        a2 += __shfl_down_sync(0xFFFFFFFFu, a2, o);
    }
    int w = t >> 5;
    if ((t & 31) == 0) { ssum[w * 3] = a0; ssum[w * 3 + 1] = a1; ssum[w * 3 + 2] = a2; }
    __syncthreads();
    if (t == 0) {
        float l0 = bl[0], l1 = bl[1], l2 = bl[2];
#pragma unroll
        for (int k = 0; k < 4; k++) {
            l0 += ssum[k * 3]; l1 += ssum[k * 3 + 1]; l2 += ssum[k * 3 + 2];
        }
        float mx = fmaxf(l0, fmaxf(l1, l2));
        float lse = mx + logf(expf(l0 - mx) + expf(l1 - mx) + expf(l2 - mx));
        out[g * 3 + 0] = l0 - lse;
        out[g * 3 + 1] = l1 - lse;
        out[g * 3 + 2] = l2 - lse;
    }
}

// ---------------- launcher (6 kernels) ----------------
extern "C" void kernel_launch(void* const* d_in, const int* in_sizes, int n_in,
                              void* d_out, int out_size) {
    const float* x   = (const float*)d_in[0];
    const void*  ei  = d_in[1];
    const void*  bi  = d_in[2];
    const float* W1  = (const float*)d_in[3];
    const float* b1  = (const float*)d_in[4];
    const float* g1  = (const float*)d_in[5];
    const float* be1 = (const float*)d_in[6];
    const float* W2  = (const float*)d_in[7];
    const float* b2  = (const float*)d_in[8];
    const float* g2  = (const float*)d_in[9];
    const float* be2 = (const float*)d_in[10];
    const float* W3  = (const float*)d_in[11];
    const float* b3  = (const float*)d_in[12];
    const float* g3  = (const float*)d_in[13];
    const float* be3 = (const float*)d_in[14];
    const float* Wl  = (const float*)d_in[15];
    const float* bl  = (const float*)d_in[16];
    float* out = (float*)d_out;

    const int T = 256;
    const int G  = 1184;
    const int L1B = (NN * 2 + T - 1) / T;

    k_prepcount<<<NBLK, T>>>(ei, bi);
    k_scanfill<<<NBLK, T>>>(ei, x);
    k_l1<<<L1B, T>>>(W1, b1, g1, be1);
    k_l2<<<G, T>>>(W2, b2, g2, be2);
    k_l3<<<G, T>>>(W3, b3, g3, be3);
    k_poolhead<<<NG, 128>>>(Wl, bl, out);
}

// round 15
// speedup vs baseline: 1.0869x; 1.0244x over previous
#include <cuda_runtime.h>
#include <cuda_fp16.h>
#include <math_constants.h>

// ---------------- problem constants ----------------
#define NN 100000      // nodes
#define NE 3200000     // edges
#define NG 512         // graphs
#define BN_EPS 1e-5f
#define NBLK ((NN + 255) / 256)   // 391

typedef unsigned long long ull;

// ---------------- packed f32x2 helpers ----------------
__device__ __forceinline__ ull pack2(float lo, float hi) {
    ull r; asm("mov.b64 %0, {%1, %2};" : "=l"(r) : "f"(lo), "f"(hi)); return r;
}
__device__ __forceinline__ ull dup2(float v) {
    ull r; asm("mov.b64 %0, {%1, %1};" : "=l"(r) : "f"(v)); return r;
}
__device__ __forceinline__ void unpack2(ull v, float& lo, float& hi) {
    asm("mov.b64 {%0, %1}, %2;" : "=f"(lo), "=f"(hi) : "l"(v));
}
__device__ __forceinline__ void ffma2(ull& d, ull a, ull b) {
    asm("fma.rn.f32x2 %0, %1, %2, %0;" : "+l"(d) : "l"(a), "l"(b));
}

// ---------------- device scratch (no allocs allowed) ----------------
__device__ int    d_cnt[NN];
__device__ int    d_rowptr[NN + 1];
__device__ int    d_wp[NN];
__device__ ull    d_tile[512];              // lookback scan state
__device__ int    d_csr[NE];                // src index only (4B/edge)
__device__ float  d_dis[NN];
__device__ float4 d_z[NN];                  // (x0*dis, x1*dis, dis, 0)
__device__ float  d_T[NN];                  // dis_i + sum_{s in N(i)} dis_s
__device__ float  d_u1[(size_t)NN * 8];     // y1 * dis (fp32)
__device__ __half d_u2h[(size_t)NN * 32];   // y2 * dis (fp16, 64B rows)
__device__ __half d_y3h[(size_t)NN * 128];  // raw y3 (fp16)
__device__ float  d_stats[256];
__device__ float  d_scale[128];
__device__ float  d_shift[128];
__device__ int    d_gstart[NG];
__device__ int    d_gend[NG];
__device__ int    d_is64_edge;
__device__ int    d_is64_batch;
__device__ int    d_tick;
__device__ int    d_bar;    // scanfill barrier (zeroed by prepcount)
__device__ int    d_bar2;   // prepcount barrier (zeroed by previous poolhead; static 0 first run)

// ---------------- BN finalize epilogue ----------------
__device__ __forceinline__ void bn_finalize(int FO, const float* gam, const float* bet) {
    __threadfence();
    __shared__ int isLast;
    if (threadIdx.x == 0) isLast = (atomicAdd(&d_tick, 1) == (int)gridDim.x - 1);
    __syncthreads();
    if (isLast) {
        if ((int)threadIdx.x < FO) {
            int c = threadIdx.x;
            float sum = atomicAdd(&d_stats[c], 0.f);
            float sq  = atomicAdd(&d_stats[128 + c], 0.f);
            float m   = sum * (1.0f / NN);
            float var = sq * (1.0f / NN) - m * m;
            float scv = gam[c] * rsqrtf(var + BN_EPS);
            d_scale[c] = scv;
            d_shift[c] = bet[c] - m * scv;
            d_stats[c] = 0.f;
            d_stats[128 + c] = 0.f;
        }
        if (threadIdx.x == 0) d_tick = 0;
    }
}

// ---------------- prep (zero + detect) + grid barrier + count/bounds ----------------
__global__ void k_prepcount(const void* ei, const void* bi) {
    int i = blockIdx.x * blockDim.x + threadIdx.x;
    if (i < NN) d_cnt[i] = 0;
    if (i < 512) d_tile[i] = 0ULL;
    if (i < 256) d_stats[i] = 0.f;
    if (i == 0) { d_tick = 0; d_bar = 0; }
    if (blockIdx.x == 0) {
        long long v = ((const long long*)ei)[(size_t)threadIdx.x * 6000];
        int ok = (v >= 0 && v < NN);
        ok = __syncthreads_and(ok);
        if (threadIdx.x == 0) d_is64_edge = ok;
    } else if (blockIdx.x == 1) {
        long long v = ((const long long*)bi)[(size_t)threadIdx.x * 195];
        int ok = (v >= 0 && v < NG);
        ok = __syncthreads_and(ok);
        if (threadIdx.x == 0) d_is64_batch = ok;
    }
    __threadfence();
    __syncthreads();
    if (threadIdx.x == 0) {
        atomicAdd(&d_bar2, 1);
        while (*(volatile int*)&d_bar2 < (int)gridDim.x) {}
    }
    __syncthreads();
    __threadfence();
    int e64 = d_is64_edge, b64 = d_is64_batch;
    int stride = gridDim.x * blockDim.x;
    for (int e = i; e < NE; e += stride) {
        int d;
        if (e64) d = (int)((const long long*)ei)[(size_t)NE + e];
        else     d = ((const int*)ei)[NE + e];
        atomicAdd(&d_cnt[d], 1);
    }
    if (i < NN) {
        int g, gp, gn;
        if (b64) {
            const long long* p = (const long long*)bi;
            g  = (int)p[i];
            gp = (i > 0)      ? (int)p[i - 1] : -1;
            gn = (i < NN - 1) ? (int)p[i + 1] : NG;
        } else {
            const int* p = (const int*)bi;
            g  = p[i];
            gp = (i > 0)      ? p[i - 1] : -1;
            gn = (i < NN - 1) ? p[i + 1] : NG;
        }
        if (g != gp) d_gstart[g] = i;
        if (g != gn) d_gend[g] = i + 1;
    }
}

// ---------------- scan (lookback) + grid barrier + z build + CSR fill ----------------
__global__ void k_scanfill(const void* ei, const float* __restrict__ x) {
    __shared__ int s[256];
    __shared__ int sExcl;
    int b = blockIdx.x, t = threadIdx.x;
    int i = b * 256 + t;
    int orig = (i < NN) ? d_cnt[i] : 0;
    s[t] = orig;
    __syncthreads();
    for (int o = 1; o < 256; o <<= 1) {
        int u = (t >= o) ? s[t - o] : 0;
        __syncthreads();
        s[t] += u;
        __syncthreads();
    }
    int incl = s[t];
    int agg  = s[255];
    if (t == 0) {
        if (b == 0) {
            sExcl = 0;
            *(volatile ull*)&d_tile[0] = (2ULL << 32) | (unsigned)agg;
        } else {
            *(volatile ull*)&d_tile[b] = (1ULL << 32) | (unsigned)agg;
            int excl = 0, p = b - 1;
            while (1) {
                ull v;
                do { v = *(volatile ull*)&d_tile[p]; } while ((unsigned)(v >> 32) == 0u);
                excl += (int)(unsigned)v;
                if ((unsigned)(v >> 32) == 2u) break;
                p--;
            }
            *(volatile ull*)&d_tile[b] = (2ULL << 32) | (unsigned)(excl + agg);
            sExcl = excl;
        }
    }
    __syncthreads();
    int ex = sExcl + incl - orig;
    float di_reg = rsqrtf((float)(orig + 1));
    if (i < NN) {
        d_rowptr[i] = ex;
        d_wp[i] = ex;
        d_dis[i] = di_reg;
        float2 xv = ((const float2*)x)[i];
        d_z[i] = make_float4(xv.x * di_reg, xv.y * di_reg, di_reg, 0.f);
    }
    if (i == 0) d_rowptr[NN] = NE;
    __threadfence();
    __syncthreads();
    if (t == 0) {
        atomicAdd(&d_bar, 1);
        while (*(volatile int*)&d_bar < (int)gridDim.x) {}
    }
    __syncthreads();
    __threadfence();
    int stride = gridDim.x * blockDim.x;
    for (int e = b * 256 + t; e < NE; e += stride) {
        int sN, dN;
        if (d_is64_edge) {
            const long long* p = (const long long*)ei;
            sN = (int)p[e];
            dN = (int)p[(size_t)NE + e];
        } else {
            const int* p = (const int*)ei;
            sN = p[e];
            dN = p[NE + e];
        }
        int pos = atomicAdd(&d_wp[dN], 1);
        d_csr[pos] = sN;
    }
}

// ---------------- layer 1: agg(z) 2-threads/node + GEMM 2->8 + relu + T + BN stats ----------------
__global__ void k_l1(const float* __restrict__ W1, const float* __restrict__ b1,
                     const float* __restrict__ g1, const float* __restrict__ be1) {
    __shared__ float sW[16], sb[8], sst[32];
    if (threadIdx.x < 16) sW[threadIdx.x] = W1[threadIdx.x];
    if (threadIdx.x < 8)  sb[threadIdx.x] = b1[threadIdx.x];
    if (threadIdx.x < 32) sst[threadIdx.x] = 0.f;
    __syncthreads();
    int gid = blockIdx.x * blockDim.x + threadIdx.x;
    int i   = gid >> 1;
    int sub = gid & 1;
    bool act = i < NN;
    float ax = 0.f, ay = 0.f, S = 0.f, di = 0.f;
    int e = 0, end = 0;
    if (act) {
        int beg = d_rowptr[i];
        end = d_rowptr[i + 1];
        e = beg + sub;
        if (sub == 0) {
            float4 zi = d_z[i];
            ax = zi.x;
            ay = zi.y;
            di = zi.z;
        }
    }
    for (; e + 6 < end; e += 8) {
        int c0 = __ldg(&d_csr[e]),     c1 = __ldg(&d_csr[e + 2]);
        int c2 = __ldg(&d_csr[e + 4]), c3 = __ldg(&d_csr[e + 6]);
        float4 z0 = __ldg(&d_z[c0]);
        float4 z1 = __ldg(&d_z[c1]);
        float4 z2 = __ldg(&d_z[c2]);
        float4 z3 = __ldg(&d_z[c3]);
        ax += z0.x + z1.x + z2.x + z3.x;
        ay += z0.y + z1.y + z2.y + z3.y;
        S  += z0.z + z1.z + z2.z + z3.z;
    }
    for (; e < end; e += 2) {
        float4 z = __ldg(&d_z[__ldg(&d_csr[e])]);
        ax += z.x;
        ay += z.y;
        S  += z.z;
    }
    ax += __shfl_xor_sync(0xFFFFFFFFu, ax, 1);
    ay += __shfl_xor_sync(0xFFFFFFFFu, ay, 1);
    S  += __shfl_xor_sync(0xFFFFFFFFu, S, 1);
    float o[8];
#pragma unroll
    for (int k = 0; k < 8; k++) o[k] = 0.f;
    if (act && sub == 0) {
        d_T[i] = di + S;
        float gx = ax * di, gy = ay * di;
#pragma unroll
        for (int k = 0; k < 8; k++)
            o[k] = fmaxf(fmaf(gx, sW[k], fmaf(gy, sW[8 + k], sb[k])), 0.f);
        float4* yo = (float4*)(d_u1 + (size_t)i * 8);
        yo[0] = make_float4(o[0] * di, o[1] * di, o[2] * di, o[3] * di);
        yo[1] = make_float4(o[4] * di, o[5] * di, o[6] * di, o[7] * di);
    }
#pragma unroll
    for (int k = 0; k < 8; k++) {
        float s = o[k], q = o[k] * o[k];
#pragma unroll
        for (int off = 16; off; off >>= 1) {
            s += __shfl_xor_sync(0xFFFFFFFFu, s, off);
            q += __shfl_xor_sync(0xFFFFFFFFu, q, off);
        }
        if ((threadIdx.x & 31) == 0) {
            atomicAdd(&sst[k], s);
            atomicAdd(&sst[16 + k], q);
        }
    }
    __syncthreads();
    if (threadIdx.x < 8) {
        atomicAdd(&d_stats[threadIdx.x], sst[threadIdx.x]);
        atomicAdd(&d_stats[128 + threadIdx.x], sst[16 + threadIdx.x]);
    }
    bn_finalize(8, g1, be1);
}

// ---------------- layer 2: 4-lane/node float2 agg + f32x2 GEMM 8->32 + relu + BN stats ----------------
// lane group of 4 per node (8 nodes/warp); lane ln2 owns feature pair (2*ln2, 2*ln2+1)
// and output channels ln2*8 .. ln2*8+7.
__global__ void k_l2(const float* __restrict__ W2, const float* __restrict__ b2,
                     const float* __restrict__ g2, const float* __restrict__ be2) {
    __shared__ ull   sWu[128];     // 8 rows x 32 floats = 8 x 16 ull (row-major)
    __shared__ float sb[32], sst[64];
    for (int k = threadIdx.x; k < 128; k += blockDim.x) sWu[k] = ((const ull*)W2)[k];
    if (threadIdx.x < 32) sb[threadIdx.x] = b2[threadIdx.x];
    if (threadIdx.x < 64) sst[threadIdx.x] = 0.f;
    __syncthreads();
    int lane = threadIdx.x & 31;
    int sub  = lane >> 2;          // node slot (0..7)
    int ln2  = lane & 3;           // feature-pair / channel-octet index
    int gbase = lane & ~3;
    int gwarp  = (blockIdx.x * blockDim.x + threadIdx.x) >> 5;
    int nwarps = (gridDim.x * blockDim.x) >> 5;
    float sc0 = d_scale[ln2 * 2],     sh0 = d_shift[ln2 * 2];
    float sc1 = d_scale[ln2 * 2 + 1], sh1 = d_shift[ln2 * 2 + 1];
    ull bias[4];
#pragma unroll
    for (int k = 0; k < 4; k++) bias[k] = pack2(sb[ln2 * 8 + 2 * k], sb[ln2 * 8 + 2 * k + 1]);
    float lsum[8], lsq[8];
#pragma unroll
    for (int k = 0; k < 8; k++) { lsum[k] = 0.f; lsq[k] = 0.f; }
    const float2* u1v = (const float2*)d_u1;
    for (int n0 = gwarp * 8; n0 < NN; n0 += nwarps * 8) {
        int node = n0 + sub;
        bool act = node < NN;
        int e = 0, end = 0;
        float a0x = 0.f, a0y = 0.f, a1x = 0.f, a1y = 0.f, di = 0.f, Tv = 0.f;
        if (act) {
            di = d_dis[node];
            Tv = d_T[node];
            e = d_rowptr[node];
            end = d_rowptr[node + 1];
            float2 s2 = __ldg(u1v + node * 4 + ln2);    // self (u has dis folded)
            a0x = s2.x; a0y = s2.y;
        }
        for (; e + 8 <= end; e += 8) {
            int c0 = __ldg(&d_csr[e]),     c1 = __ldg(&d_csr[e + 1]);
            int c2 = __ldg(&d_csr[e + 2]), c3 = __ldg(&d_csr[e + 3]);
            int c4 = __ldg(&d_csr[e + 4]), c5 = __ldg(&d_csr[e + 5]);
            int c6 = __ldg(&d_csr[e + 6]), c7 = __ldg(&d_csr[e + 7]);
            float2 v0 = __ldg(u1v + c0 * 4 + ln2);
            float2 v1 = __ldg(u1v + c1 * 4 + ln2);
            float2 v2 = __ldg(u1v + c2 * 4 + ln2);
            float2 v3 = __ldg(u1v + c3 * 4 + ln2);
            float2 v4 = __ldg(u1v + c4 * 4 + ln2);
            float2 v5 = __ldg(u1v + c5 * 4 + ln2);
            float2 v6 = __ldg(u1v + c6 * 4 + ln2);
            float2 v7 = __ldg(u1v + c7 * 4 + ln2);
            a0x += (v0.x + v2.x) + (v4.x + v6.x);
            a0y += (v0.y + v2.y) + (v4.y + v6.y);
            a1x += (v1.x + v3.x) + (v5.x + v7.x);
            a1y += (v1.y + v3.y) + (v5.y + v7.y);
        }
        for (; e < end; e++) {
            float2 v = __ldg(u1v + __ldg(&d_csr[e]) * 4 + ln2);
            a0x += v.x;
            a0y += v.y;
        }
        float Ux = a0x + a1x, Uy = a0y + a1y;
        float gx = di * fmaf(sc0, Ux, sh0 * Tv);
        float gy = di * fmaf(sc1, Uy, sh1 * Tv);
        // GEMM 8->32 (packed): gather 8 agg features from the 4-lane group
        ull a[4];
#pragma unroll
        for (int k = 0; k < 4; k++) a[k] = bias[k];
#pragma unroll
        for (int f2 = 0; f2 < 4; f2++) {
            float g0 = __shfl_sync(0xFFFFFFFFu, gx, gbase + f2);
            float g1 = __shfl_sync(0xFFFFFFFFu, gy, gbase + f2);
            ull d0 = dup2(g0), d1 = dup2(g1);
            const ull* w0 = &sWu[(2 * f2) * 16 + ln2 * 4];
            const ull* w1 = &sWu[(2 * f2 + 1) * 16 + ln2 * 4];
#pragma unroll
            for (int k = 0; k < 4; k++) {
                ffma2(a[k], d0, w0[k]);
                ffma2(a[k], d1, w1[k]);
            }
        }
        if (act) {
            float v[8];
#pragma unroll
            for (int k = 0; k < 4; k++) {
                unpack2(a[k], v[2 * k], v[2 * k + 1]);
            }
#pragma unroll
            for (int k = 0; k < 8; k++) v[k] = fmaxf(v[k], 0.f);
            __half2 h0 = __floats2half2_rn(v[0] * di, v[1] * di);
            __half2 h1 = __floats2half2_rn(v[2] * di, v[3] * di);
            __half2 h2 = __floats2half2_rn(v[4] * di, v[5] * di);
            __half2 h3 = __floats2half2_rn(v[6] * di, v[7] * di);
            uint4 pk = make_uint4(*(unsigned*)&h0, *(unsigned*)&h1,
                                  *(unsigned*)&h2, *(unsigned*)&h3);
            ((uint4*)(d_u2h + (size_t)node * 32))[ln2] = pk;
#pragma unroll
            for (int k = 0; k < 8; k++) { lsum[k] += v[k]; lsq[k] += v[k] * v[k]; }
        }
    }
    // reduce stats across the 8 node-groups (lanes sharing ln2)
#pragma unroll
    for (int off = 4; off <= 16; off <<= 1) {
#pragma unroll
        for (int k = 0; k < 8; k++) {
            lsum[k] += __shfl_xor_sync(0xFFFFFFFFu, lsum[k], off);
            lsq[k]  += __shfl_xor_sync(0xFFFFFFFFu, lsq[k], off);
        }
    }
    if (lane < 4) {
#pragma unroll
        for (int k = 0; k < 8; k++) {
            atomicAdd(&sst[ln2 * 8 + k], lsum[k]);
            atomicAdd(&sst[32 + ln2 * 8 + k], lsq[k]);
        }
    }
    __syncthreads();
    if (threadIdx.x < 32) {
        atomicAdd(&d_stats[threadIdx.x], sst[threadIdx.x]);
        atomicAdd(&d_stats[128 + threadIdx.x], sst[32 + threadIdx.x]);
    }
    bn_finalize(32, g2, be2);
}

// ---------------- layer 3: plain-sum fp16 agg + GEMM 32->128 (4-node, f32x2) + BN stats ----------------
__global__ void k_l3(const float* __restrict__ W3, const float* __restrict__ b3,
                     const float* __restrict__ g3, const float* __restrict__ be3) {
    __shared__ ull   sW[2048];
    __shared__ float sb[128];
    __shared__ float bs[256];
    for (int k = threadIdx.x; k < 2048; k += blockDim.x)
        sW[k] = ((const ull*)W3)[k];
    if (threadIdx.x < 128) sb[threadIdx.x] = b3[threadIdx.x];
    bs[threadIdx.x] = 0.f;
    __syncthreads();
    int lane = threadIdx.x & 31;
    int gwarp  = (blockIdx.x * blockDim.x + threadIdx.x) >> 5;
    int nwarps = (gridDim.x * blockDim.x) >> 5;
    float sc = d_scale[lane], sh = d_shift[lane];
    ull bias01 = pack2(sb[lane * 4], sb[lane * 4 + 1]);
    ull bias23 = pack2(sb[lane * 4 + 2], sb[lane * 4 + 3]);
    float ls0 = 0.f, ls1 = 0.f, ls2 = 0.f, ls3 = 0.f;
    float lq0 = 0.f, lq1 = 0.f, lq2 = 0.f, lq3 = 0.f;
    for (int n0 = gwarp * 4; n0 < NN; n0 += nwarps * 4) {
        float accs[4];
#pragma unroll
        for (int nb = 0; nb < 4; nb++) {
            int node = n0 + nb;
            float acc0 = 0.f, acc1 = 0.f, di = 0.f, Tv = 0.f;
            if (node < NN) {
                di = d_dis[node];
                Tv = d_T[node];
                int e = d_rowptr[node], end = d_rowptr[node + 1];
                acc0 = __half2float(d_u2h[(size_t)node * 32 + lane]);
                for (; e + 8 <= end; e += 8) {
                    int c0 = __ldg(&d_csr[e]),     c1 = __ldg(&d_csr[e + 1]);
                    int c2 = __ldg(&d_csr[e + 2]), c3 = __ldg(&d_csr[e + 3]);
                    int c4 = __ldg(&d_csr[e + 4]), c5 = __ldg(&d_csr[e + 5]);
                    int c6 = __ldg(&d_csr[e + 6]), c7 = __ldg(&d_csr[e + 7]);
                    float h0 = __half2float(d_u2h[(size_t)c0 * 32 + lane]);
                    float h1 = __half2float(d_u2h[(size_t)c1 * 32 + lane]);
                    float h2 = __half2float(d_u2h[(size_t)c2 * 32 + lane]);
                    float h3 = __half2float(d_u2h[(size_t)c3 * 32 + lane]);
                    float h4 = __half2float(d_u2h[(size_t)c4 * 32 + lane]);
                    float h5 = __half2float(d_u2h[(size_t)c5 * 32 + lane]);
                    float h6 = __half2float(d_u2h[(size_t)c6 * 32 + lane]);
                    float h7 = __half2float(d_u2h[(size_t)c7 * 32 + lane]);
                    acc0 += (h0 + h2) + (h4 + h6);
                    acc1 += (h1 + h3) + (h5 + h7);
                }
                for (; e < end; e++) {
                    acc0 += __half2float(d_u2h[(size_t)__ldg(&d_csr[e]) * 32 + lane]);
                }
            }
            float U = acc0 + acc1;
            accs[nb] = di * fmaf(sc, U, sh * Tv);
        }
        ull a01[4], a23[4];
#pragma unroll
        for (int nb = 0; nb < 4; nb++) { a01[nb] = bias01; a23[nb] = bias23; }
#pragma unroll
        for (int f = 0; f < 32; f++) {
            ull w01 = sW[f * 64 + lane * 2];
            ull w23 = sW[f * 64 + lane * 2 + 1];
#pragma unroll
            for (int nb = 0; nb < 4; nb++) {
                ull avv = dup2(__shfl_sync(0xFFFFFFFFu, accs[nb], f));
                ffma2(a01[nb], avv, w01);
                ffma2(a23[nb], avv, w23);
            }
        }
#pragma unroll
        for (int nb = 0; nb < 4; nb++) {
            int node = n0 + nb;
            if (node >= NN) break;
            float v0, v1, v2, v3;
            unpack2(a01[nb], v0, v1);
            unpack2(a23[nb], v2, v3);
            v0 = fmaxf(v0, 0.f); v1 = fmaxf(v1, 0.f);
            v2 = fmaxf(v2, 0.f); v3 = fmaxf(v3, 0.f);
            __half2 h01 = __floats2half2_rn(v0, v1);
            __half2 h23 = __floats2half2_rn(v2, v3);
            uint2 pk = make_uint2(*(unsigned*)&h01, *(unsigned*)&h23);
            ((uint2*)(d_y3h + (size_t)node * 128))[lane] = pk;
            ls0 += v0; lq0 += v0 * v0;
            ls1 += v1; lq1 += v1 * v1;
            ls2 += v2; lq2 += v2 * v2;
            ls3 += v3; lq3 += v3 * v3;
        }
    }
    atomicAdd(&bs[lane * 4 + 0], ls0); atomicAdd(&bs[128 + lane * 4 + 0], lq0);
    atomicAdd(&bs[lane * 4 + 1], ls1); atomicAdd(&bs[128 + lane * 4 + 1], lq1);
    atomicAdd(&bs[lane * 4 + 2], ls2); atomicAdd(&bs[128 + lane * 4 + 2], lq2);
    atomicAdd(&bs[lane * 4 + 3], ls3); atomicAdd(&bs[128 + lane * 4 + 3], lq3);
    __syncthreads();
    atomicAdd(&d_stats[threadIdx.x], bs[threadIdx.x]);
    bn_finalize(128, g3, be3);
}

// ---------------- fused max-pool (BN folded, fp16 reads) + linear + log_softmax ----------------
__global__ void k_poolhead(const float* __restrict__ Wl, const float* __restrict__ bl,
                           float* __restrict__ out) {
    __shared__ float ssum[12];
    int g = blockIdx.x, t = threadIdx.x;
    if (g == 0 && t == 0) d_bar2 = 0;
    float sc = d_scale[t], sh = d_shift[t];
    float m = -CUDART_INF_F;
    int s = d_gstart[g], e = d_gend[g];
    int i = s;
    for (; i + 4 <= e; i += 4) {
        float v0 = __half2float(d_y3h[(size_t)(i + 0) * 128 + t]);
        float v1 = __half2float(d_y3h[(size_t)(i + 1) * 128 + t]);
        float v2 = __half2float(d_y3h[(size_t)(i + 2) * 128 + t]);
        float v3 = __half2float(d_y3h[(size_t)(i + 3) * 128 + t]);
        m = fmaxf(m, fmaxf(fmaxf(v0, v1), fmaxf(v2, v3)));
    }
    for (; i < e; i++) m = fmaxf(m, __half2float(d_y3h[(size_t)i * 128 + t]));
    float p = fmaf(m, sc, sh);
    float a0 = p * Wl[t * 3 + 0];
    float a1 = p * Wl[t * 3 + 1];
    float a2 = p * Wl[t * 3 + 2];
#pragma unroll
    for (int o = 16; o > 0; o >>= 1) {
        a0 += __shfl_down_sync(0xFFFFFFFFu, a0, o);
        a1 += __shfl_down_sync(0xFFFFFFFFu, a1, o);
        a2 += __shfl_down_sync(0xFFFFFFFFu, a2, o);
    }
    int w = t >> 5;
    if ((t & 31) == 0) { ssum[w * 3] = a0; ssum[w * 3 + 1] = a1; ssum[w * 3 + 2] = a2; }
    __syncthreads();
    if (t == 0) {
        float l0 = bl[0], l1 = bl[1], l2 = bl[2];
#pragma unroll
        for (int k = 0; k < 4; k++) {
            l0 += ssum[k * 3]; l1 += ssum[k * 3 + 1]; l2 += ssum[k * 3 + 2];
        }
        float mx = fmaxf(l0, fmaxf(l1, l2));
        float lse = mx + logf(expf(l0 - mx) + expf(l1 - mx) + expf(l2 - mx));
        out[g * 3 + 0] = l0 - lse;
        out[g * 3 + 1] = l1 - lse;
        out[g * 3 + 2] = l2 - lse;
    }
}

// ---------------- launcher (6 kernels) ----------------
extern "C" void kernel_launch(void* const* d_in, const int* in_sizes, int n_in,
                              void* d_out, int out_size) {
    const void*  ei  = d_in[1];
    const void*  bi  = d_in[2];
    const float* x   = (const float*)d_in[0];
    const float* W1  = (const float*)d_in[3];
    const float* b1  = (const float*)d_in[4];
    const float* g1  = (const float*)d_in[5];
    const float* be1 = (const float*)d_in[6];
    const float* W2  = (const float*)d_in[7];
    const float* b2  = (const float*)d_in[8];
    const float* g2  = (const float*)d_in[9];
    const float* be2 = (const float*)d_in[10];
    const float* W3  = (const float*)d_in[11];
    const float* b3  = (const float*)d_in[12];
    const float* g3  = (const float*)d_in[13];
    const float* be3 = (const float*)d_in[14];
    const float* Wl  = (const float*)d_in[15];
    const float* bl  = (const float*)d_in[16];
    float* out = (float*)d_out;

    const int T = 256;
    const int G  = 1184;
    const int L1B = (NN * 2 + T - 1) / T;

    k_prepcount<<<NBLK, T>>>(ei, bi);
    k_scanfill<<<NBLK, T>>>(ei, x);
    k_l1<<<L1B, T>>>(W1, b1, g1, be1);
    k_l2<<<G, T>>>(W2, b2, g2, be2);
    k_l3<<<G, T>>>(W3, b3, g3, be3);
    k_poolhead<<<NG, 128>>>(Wl, bl, out);
}